// round 2
// baseline (speedup 1.0000x reference)
#include <cuda_runtime.h>

#define N_NODES 100000
#define N_EDGES 1600000
#define N_EP    200000
#define N_EN    200000
#define IN_CH   256
#define HID     128
#define N_CLS   10
#define CAP     64
#define NODE_OUT_ELEMS (N_NODES * N_CLS)

// ---------------- static device scratch (no allocation allowed) ----------------
__device__ int   g_counts[N_NODES];
__device__ int   g_cursor[N_NODES];
__device__ float g_dinv[N_NODES];
__device__ int   g_srcbuf[(size_t)N_NODES * CAP];     // 25.6 MB
__device__ float g_tmp[(size_t)N_NODES * 128];        // 51.2 MB  (x@W buffer)
__device__ float g_h[(size_t)N_NODES * 128];          // 51.2 MB  (aggregated h)

// ---------------- graph preprocessing ----------------
__global__ void k_zero() {
    int i = blockIdx.x * blockDim.x + threadIdx.x;
    if (i < N_NODES) { g_counts[i] = 0; g_cursor[i] = 0; }
}

__global__ void k_count(const int* __restrict__ ei) {
    int i = blockIdx.x * blockDim.x + threadIdx.x;
    if (i < N_EDGES) atomicAdd(&g_counts[ei[N_EDGES + i]], 1);
}

__global__ void k_dinv() {
    int i = blockIdx.x * blockDim.x + threadIdx.x;
    if (i < N_NODES) g_dinv[i] = rsqrtf((float)g_counts[i] + 1.0f);
}

__global__ void k_bucket(const int* __restrict__ ei) {
    int i = blockIdx.x * blockDim.x + threadIdx.x;
    if (i < N_EDGES) {
        int d = ei[N_EDGES + i];
        int slot = atomicAdd(&g_cursor[d], 1);
        if (slot < CAP) g_srcbuf[(size_t)d * CAP + slot] = ei[i];
    }
}

// ---------------- dense GEMM: out[N,128] = A[N,K] @ W[K,128] ----------------
// Block = 128 threads, computes 16 nodes x 128 cols. A tile staged in smem.
template <int K, bool USE_H>
__global__ void k_gemm(const float* __restrict__ A, const float* __restrict__ W) {
    __shared__ float xs[16][K];
    const float* Ain = USE_H ? g_h : A;
    int node0 = blockIdx.x * 16;
    int tid = threadIdx.x;

    const float* arow = Ain + (size_t)node0 * K;
    for (int i = tid; i < 16 * K; i += 128)
        xs[i / K][i % K] = arow[i];
    __syncthreads();

    float acc[16];
#pragma unroll
    for (int r = 0; r < 16; r++) acc[r] = 0.0f;

#pragma unroll 4
    for (int k = 0; k < K; k++) {
        float wj = __ldg(&W[k * 128 + tid]);
#pragma unroll
        for (int r = 0; r < 16; r++) acc[r] += xs[r][k] * wj;
    }

#pragma unroll
    for (int r = 0; r < 16; r++)
        g_tmp[(size_t)(node0 + r) * 128 + tid] = acc[r];
}

// ---------------- aggregation: h[v] = sum_{s->v} norm * xw[s] (+self) + bias ----------------
// One warp per node; lane owns 4 contiguous floats (float4).
template <bool RELU>
__global__ void k_agg(const float* __restrict__ bias) {
    int w = (blockIdx.x * blockDim.x + threadIdx.x) >> 5;
    int lane = threadIdx.x & 31;
    if (w >= N_NODES) return;

    const float4* xw4 = (const float4*)g_tmp;
    float dv = g_dinv[w];
    float sw = dv * dv;

    float4 a = xw4[(size_t)w * 32 + lane];
    float4 acc = make_float4(a.x * sw, a.y * sw, a.z * sw, a.w * sw);

    int cnt = g_counts[w];
    if (cnt > CAP) cnt = CAP;
    const int* sb = &g_srcbuf[(size_t)w * CAP];
    for (int e = 0; e < cnt; e++) {
        int s = __ldg(&sb[e]);
        float wt = __ldg(&g_dinv[s]) * dv;
        float4 v = xw4[(size_t)s * 32 + lane];
        acc.x += v.x * wt; acc.y += v.y * wt;
        acc.z += v.z * wt; acc.w += v.w * wt;
    }

    float4 b = ((const float4*)bias)[lane];
    acc.x += b.x; acc.y += b.y; acc.z += b.z; acc.w += b.w;
    if (RELU) {
        acc.x = fmaxf(acc.x, 0.0f); acc.y = fmaxf(acc.y, 0.0f);
        acc.z = fmaxf(acc.z, 0.0f); acc.w = fmaxf(acc.w, 0.0f);
    }
    ((float4*)g_h)[(size_t)w * 32 + lane] = acc;
}

// ---------------- node head: log_softmax(relu(h) @ Wcls + bcls) ----------------
__global__ void k_nodehead(const float* __restrict__ Wc, const float* __restrict__ bc,
                           float* __restrict__ out) {
    int v = (blockIdx.x * blockDim.x + threadIdx.x) >> 5;
    int lane = threadIdx.x & 31;
    if (v >= N_NODES) return;

    float4 hv = ((const float4*)g_h)[(size_t)v * 32 + lane];
    float r0 = fmaxf(hv.x, 0.0f), r1 = fmaxf(hv.y, 0.0f);
    float r2 = fmaxf(hv.z, 0.0f), r3 = fmaxf(hv.w, 0.0f);
    int k0 = lane * 4;

    float logits[N_CLS];
#pragma unroll
    for (int c = 0; c < N_CLS; c++) {
        float p = r0 * __ldg(&Wc[(k0 + 0) * N_CLS + c])
                + r1 * __ldg(&Wc[(k0 + 1) * N_CLS + c])
                + r2 * __ldg(&Wc[(k0 + 2) * N_CLS + c])
                + r3 * __ldg(&Wc[(k0 + 3) * N_CLS + c]);
#pragma unroll
        for (int o = 16; o > 0; o >>= 1) p += __shfl_xor_sync(0xffffffffu, p, o);
        logits[c] = p + __ldg(&bc[c]);
    }

    float m = logits[0];
#pragma unroll
    for (int c = 1; c < N_CLS; c++) m = fmaxf(m, logits[c]);
    float se = 0.0f;
#pragma unroll
    for (int c = 0; c < N_CLS; c++) se += expf(logits[c] - m);
    float lse = m + logf(se);

    if (lane < N_CLS) {
        float val = logits[0];
#pragma unroll
        for (int c = 1; c < N_CLS; c++) if (lane == c) val = logits[c];
        out[(size_t)v * N_CLS + lane] = val - lse;
    }
}

// ---------------- link head: dot(h[s], Wl[:128]) + dot(h[d], Wl[128:]) + b ----------------
__global__ void k_link(const int* __restrict__ ep, const int* __restrict__ en,
                       const float* __restrict__ Wl, const float* __restrict__ bl,
                       float* __restrict__ out) {
    int w = (blockIdx.x * blockDim.x + threadIdx.x) >> 5;
    int lane = threadIdx.x & 31;
    if (w >= N_EP + N_EN) return;

    int s, d;
    float* o;
    if (w < N_EP) {
        s = ep[w]; d = ep[N_EP + w]; o = out + w;
    } else {
        int w2 = w - N_EP;
        s = en[w2]; d = en[N_EN + w2]; o = out + N_EP + w2;
    }

    float4 hs = ((const float4*)g_h)[(size_t)s * 32 + lane];
    float4 hd = ((const float4*)g_h)[(size_t)d * 32 + lane];
    float4 ws = ((const float4*)Wl)[lane];
    float4 wd = ((const float4*)(Wl + 128))[lane];

    float p = hs.x * ws.x + hs.y * ws.y + hs.z * ws.z + hs.w * ws.w
            + hd.x * wd.x + hd.y * wd.y + hd.z * wd.z + hd.w * wd.w;
#pragma unroll
    for (int o2 = 16; o2 > 0; o2 >>= 1) p += __shfl_xor_sync(0xffffffffu, p, o2);

    if (lane == 0) *o = p + bl[0];
}

// ---------------- launch ----------------
extern "C" void kernel_launch(void* const* d_in, const int* in_sizes, int n_in,
                              void* d_out, int out_size) {
    const float* x   = (const float*)d_in[0];
    const int*   ei  = (const int*)d_in[1];
    const int*   ep  = (const int*)d_in[2];
    const int*   en  = (const int*)d_in[3];
    const float* W1  = (const float*)d_in[4];
    const float* b1  = (const float*)d_in[5];
    const float* W2  = (const float*)d_in[6];
    const float* b2  = (const float*)d_in[7];
    const float* Wc  = (const float*)d_in[8];
    const float* bc  = (const float*)d_in[9];
    const float* Wl  = (const float*)d_in[10];
    const float* bl  = (const float*)d_in[11];
    float* out = (float*)d_out;

    // graph preprocessing
    k_zero<<<(N_NODES + 255) / 256, 256>>>();
    k_count<<<N_EDGES / 256, 256>>>(ei);
    k_dinv<<<(N_NODES + 255) / 256, 256>>>();
    k_bucket<<<N_EDGES / 256, 256>>>(ei);

    // layer 1: tmp = x @ W1 ; h = relu(agg(tmp) + b1)
    k_gemm<IN_CH, false><<<N_NODES / 16, 128>>>(x, W1);
    k_agg<true><<<N_NODES / 8, 256>>>(b1);

    // layer 2: tmp = h @ W2 ; h = agg(tmp) + b2
    k_gemm<HID, true><<<N_NODES / 16, 128>>>(nullptr, W2);
    k_agg<false><<<N_NODES / 8, 256>>>(b2);

    // heads
    k_nodehead<<<N_NODES / 8, 256>>>(Wc, bc, out);
    k_link<<<(N_EP + N_EN) / 8, 256>>>(ep, en, Wl, bl, out + NODE_OUT_ELEMS);
}

// round 3
// speedup vs baseline: 1.3127x; 1.3127x over previous
#include <cuda_runtime.h>

#define N_NODES 100000
#define N_EDGES 1600000
#define N_EP    200000
#define N_EN    200000
#define IN_CH   256
#define HID     128
#define N_CLS   10
#define CAP     64
#define NODE_OUT_ELEMS (N_NODES * N_CLS)

// ---------------- static device scratch (no allocation allowed) ----------------
__device__ int   g_cursor[N_NODES];                   // degree counts / bucket cursor
__device__ float g_dinv[N_NODES];
__device__ int   g_srcbuf[(size_t)N_NODES * CAP];     // 25.6 MB
__device__ float g_tmp[(size_t)N_NODES * 128];        // 51.2 MB  (x@W buffer)
__device__ float g_h[(size_t)N_NODES * 128];          // 51.2 MB  (aggregated h)

// ---------------- graph preprocessing ----------------
__global__ void k_zero() {
    int i = blockIdx.x * blockDim.x + threadIdx.x;
    if (i < N_NODES) g_cursor[i] = 0;
}

__global__ void k_bucket(const int* __restrict__ ei) {
    int i = blockIdx.x * blockDim.x + threadIdx.x;
    if (i < N_EDGES) {
        int d = ei[N_EDGES + i];
        int slot = atomicAdd(&g_cursor[d], 1);
        if (slot < CAP) g_srcbuf[(size_t)d * CAP + slot] = ei[i];
    }
}

__global__ void k_dinv() {
    int i = blockIdx.x * blockDim.x + threadIdx.x;
    if (i < N_NODES) g_dinv[i] = rsqrtf((float)g_cursor[i] + 1.0f);
}

// ---------------- dense GEMM: out[N,128] = A[N,K] @ W[K,128] ----------------
// 128x128 tile, 256 threads, 8x8 micro-tile per thread. A tile k-major in smem.
template <int K, bool USE_H>
__global__ void __launch_bounds__(256) k_gemm(const float* __restrict__ A,
                                              const float* __restrict__ W) {
    __shared__ float As[16][132];   // [k][row], padded: conflict-free-ish
    __shared__ float Ws[16][132];   // [k][col]
    const float* Ain = USE_H ? g_h : A;
    int node0 = blockIdx.x * 128;
    int tid = threadIdx.x;
    int tx = tid & 15;    // col group: cols tx*8 .. tx*8+7
    int ty = tid >> 4;    // row group: rows ty*8 .. ty*8+7

    float acc[8][8];
#pragma unroll
    for (int r = 0; r < 8; r++)
#pragma unroll
        for (int c = 0; c < 8; c++) acc[r][c] = 0.0f;

    for (int kc = 0; kc < K; kc += 16) {
        // Load A chunk (128 rows x 16 k), transpose into As[k][row].
        // 512 float4 loads: e = tid + i*256; row = e>>2, kvec = (e&3)*4
#pragma unroll
        for (int i = 0; i < 2; i++) {
            int e = tid + i * 256;
            int row = e >> 2, kv = (e & 3) * 4;
            int gr = node0 + row;
            if (gr > N_NODES - 1) gr = N_NODES - 1;
            float4 v = *(const float4*)&Ain[(size_t)gr * K + kc + kv];
            As[kv + 0][row] = v.x; As[kv + 1][row] = v.y;
            As[kv + 2][row] = v.z; As[kv + 3][row] = v.w;
        }
        // Load W chunk (16 k x 128 cols), same layout.
#pragma unroll
        for (int i = 0; i < 2; i++) {
            int f = tid + i * 256;
            int kr = f >> 5, c4 = (f & 31) * 4;
            *(float4*)&Ws[kr][c4] = *(const float4*)&W[(size_t)(kc + kr) * 128 + c4];
        }
        __syncthreads();

#pragma unroll
        for (int k = 0; k < 16; k++) {
            float4 a0 = *(float4*)&As[k][ty * 8];
            float4 a1 = *(float4*)&As[k][ty * 8 + 4];
            float4 w0 = *(float4*)&Ws[k][tx * 8];
            float4 w1 = *(float4*)&Ws[k][tx * 8 + 4];
            float a[8] = {a0.x, a0.y, a0.z, a0.w, a1.x, a1.y, a1.z, a1.w};
            float w[8] = {w0.x, w0.y, w0.z, w0.w, w1.x, w1.y, w1.z, w1.w};
#pragma unroll
            for (int r = 0; r < 8; r++)
#pragma unroll
                for (int c = 0; c < 8; c++) acc[r][c] += a[r] * w[c];
        }
        __syncthreads();
    }

#pragma unroll
    for (int r = 0; r < 8; r++) {
        int gr = node0 + ty * 8 + r;
        if (gr < N_NODES) {
            *(float4*)&g_tmp[(size_t)gr * 128 + tx * 8] =
                make_float4(acc[r][0], acc[r][1], acc[r][2], acc[r][3]);
            *(float4*)&g_tmp[(size_t)gr * 128 + tx * 8 + 4] =
                make_float4(acc[r][4], acc[r][5], acc[r][6], acc[r][7]);
        }
    }
}

// ---------------- aggregation: h[v] = sum_{s->v} norm * xw[s] (+self) + bias ----------------
// One warp per node; lane owns 4 contiguous floats (float4).
__device__ __forceinline__ float4 agg_node(int w, int lane, const float* __restrict__ bias) {
    const float4* xw4 = (const float4*)g_tmp;
    float dv = g_dinv[w];
    float sw = dv * dv;

    float4 a = xw4[(size_t)w * 32 + lane];
    float4 acc = make_float4(a.x * sw, a.y * sw, a.z * sw, a.w * sw);

    int cnt = g_cursor[w];
    if (cnt > CAP) cnt = CAP;
    const int* sb = &g_srcbuf[(size_t)w * CAP];
    for (int e = 0; e < cnt; e++) {
        int s = __ldg(&sb[e]);
        float wt = __ldg(&g_dinv[s]) * dv;
        float4 v = xw4[(size_t)s * 32 + lane];
        acc.x += v.x * wt; acc.y += v.y * wt;
        acc.z += v.z * wt; acc.w += v.w * wt;
    }
    float4 b = ((const float4*)bias)[lane];
    acc.x += b.x; acc.y += b.y; acc.z += b.z; acc.w += b.w;
    return acc;
}

__global__ void k_agg_relu(const float* __restrict__ bias) {
    int w = (blockIdx.x * blockDim.x + threadIdx.x) >> 5;
    int lane = threadIdx.x & 31;
    if (w >= N_NODES) return;
    float4 acc = agg_node(w, lane, bias);
    acc.x = fmaxf(acc.x, 0.0f); acc.y = fmaxf(acc.y, 0.0f);
    acc.z = fmaxf(acc.z, 0.0f); acc.w = fmaxf(acc.w, 0.0f);
    ((float4*)g_h)[(size_t)w * 32 + lane] = acc;
}

// layer-2 aggregation fused with the node-classification head
__global__ void k_agg_nodehead(const float* __restrict__ bias,
                               const float* __restrict__ Wc, const float* __restrict__ bc,
                               float* __restrict__ out) {
    int v = (blockIdx.x * blockDim.x + threadIdx.x) >> 5;
    int lane = threadIdx.x & 31;
    if (v >= N_NODES) return;

    float4 hv = agg_node(v, lane, bias);
    ((float4*)g_h)[(size_t)v * 32 + lane] = hv;   // link head needs h

    float r0 = fmaxf(hv.x, 0.0f), r1 = fmaxf(hv.y, 0.0f);
    float r2 = fmaxf(hv.z, 0.0f), r3 = fmaxf(hv.w, 0.0f);
    int k0 = lane * 4;

    float logits[N_CLS];
#pragma unroll
    for (int c = 0; c < N_CLS; c++) {
        float p = r0 * __ldg(&Wc[(k0 + 0) * N_CLS + c])
                + r1 * __ldg(&Wc[(k0 + 1) * N_CLS + c])
                + r2 * __ldg(&Wc[(k0 + 2) * N_CLS + c])
                + r3 * __ldg(&Wc[(k0 + 3) * N_CLS + c]);
#pragma unroll
        for (int o = 16; o > 0; o >>= 1) p += __shfl_xor_sync(0xffffffffu, p, o);
        logits[c] = p + __ldg(&bc[c]);
    }

    float m = logits[0];
#pragma unroll
    for (int c = 1; c < N_CLS; c++) m = fmaxf(m, logits[c]);
    float se = 0.0f;
#pragma unroll
    for (int c = 0; c < N_CLS; c++) se += expf(logits[c] - m);
    float lse = m + logf(se);

    if (lane < N_CLS) {
        float val = logits[0];
#pragma unroll
        for (int c = 1; c < N_CLS; c++) if (lane == c) val = logits[c];
        out[(size_t)v * N_CLS + lane] = val - lse;
    }
}

// ---------------- link head: dot(h[s], Wl[:128]) + dot(h[d], Wl[128:]) + b ----------------
__global__ void k_link(const int* __restrict__ ep, const int* __restrict__ en,
                       const float* __restrict__ Wl, const float* __restrict__ bl,
                       float* __restrict__ out) {
    int w = (blockIdx.x * blockDim.x + threadIdx.x) >> 5;
    int lane = threadIdx.x & 31;
    if (w >= N_EP + N_EN) return;

    int s, d;
    float* o;
    if (w < N_EP) {
        s = ep[w]; d = ep[N_EP + w]; o = out + w;
    } else {
        int w2 = w - N_EP;
        s = en[w2]; d = en[N_EN + w2]; o = out + N_EP + w2;
    }

    float4 hs = ((const float4*)g_h)[(size_t)s * 32 + lane];
    float4 hd = ((const float4*)g_h)[(size_t)d * 32 + lane];
    float4 ws = ((const float4*)Wl)[lane];
    float4 wd = ((const float4*)(Wl + 128))[lane];

    float p = hs.x * ws.x + hs.y * ws.y + hs.z * ws.z + hs.w * ws.w
            + hd.x * wd.x + hd.y * wd.y + hd.z * wd.z + hd.w * wd.w;
#pragma unroll
    for (int o2 = 16; o2 > 0; o2 >>= 1) p += __shfl_xor_sync(0xffffffffu, p, o2);

    if (lane == 0) *o = p + bl[0];
}

// ---------------- launch ----------------
extern "C" void kernel_launch(void* const* d_in, const int* in_sizes, int n_in,
                              void* d_out, int out_size) {
    const float* x   = (const float*)d_in[0];
    const int*   ei  = (const int*)d_in[1];
    const int*   ep  = (const int*)d_in[2];
    const int*   en  = (const int*)d_in[3];
    const float* W1  = (const float*)d_in[4];
    const float* b1  = (const float*)d_in[5];
    const float* W2  = (const float*)d_in[6];
    const float* b2  = (const float*)d_in[7];
    const float* Wc  = (const float*)d_in[8];
    const float* bc  = (const float*)d_in[9];
    const float* Wl  = (const float*)d_in[10];
    const float* bl  = (const float*)d_in[11];
    float* out = (float*)d_out;

    // graph preprocessing (cursor doubles as degree count)
    k_zero<<<(N_NODES + 255) / 256, 256>>>();
    k_bucket<<<N_EDGES / 256, 256>>>(ei);
    k_dinv<<<(N_NODES + 255) / 256, 256>>>();

    const int GEMM_GRID = (N_NODES + 127) / 128;

    // layer 1: tmp = x @ W1 ; h = relu(agg(tmp) + b1)
    k_gemm<IN_CH, false><<<GEMM_GRID, 256>>>(x, W1);
    k_agg_relu<<<N_NODES / 8, 256>>>(b1);

    // layer 2: tmp = h @ W2 ; h = agg(tmp) + b2 ; node head fused
    k_gemm<HID, true><<<GEMM_GRID, 256>>>(nullptr, W2);
    k_agg_nodehead<<<N_NODES / 8, 256>>>(b2, Wc, bc, out);

    // link head
    k_link<<<(N_EP + N_EN) / 8, 256>>>(ep, en, Wl, bl, out + NODE_OUT_ELEMS);
}

// round 4
// speedup vs baseline: 1.7970x; 1.3689x over previous
#include <cuda_runtime.h>
#include <cstdint>

#define N_NODES 100000
#define N_EDGES 1600000
#define N_EP    200000
#define N_EN    200000
#define IN_CH   256
#define HID     128
#define N_CLS   10
#define CAP     64
#define NODE_OUT_ELEMS (N_NODES * N_CLS)

// ---------------- static device scratch (no allocation allowed) ----------------
__device__ int   g_cursor[N_NODES];                   // degree counts / bucket cursor
__device__ float g_dinv[N_NODES];
__device__ int   g_srcbuf[(size_t)N_NODES * CAP];     // 25.6 MB
__device__ float g_tmp[(size_t)N_NODES * 128];        // 51.2 MB  (x@W buffer)
__device__ float g_h[(size_t)N_NODES * 128];          // 51.2 MB  (aggregated h)

// ---------------- graph preprocessing ----------------
__global__ void k_zero() {
    int i = blockIdx.x * blockDim.x + threadIdx.x;
    if (i < N_NODES) g_cursor[i] = 0;
}

__global__ void k_bucket(const int* __restrict__ ei) {
    int i = blockIdx.x * blockDim.x + threadIdx.x;
    if (i < N_EDGES) {
        int d = ei[N_EDGES + i];
        int slot = atomicAdd(&g_cursor[d], 1);
        if (slot < CAP) g_srcbuf[(size_t)d * CAP + slot] = ei[i];
    }
}

__global__ void k_dinv() {
    int i = blockIdx.x * blockDim.x + threadIdx.x;
    if (i < N_NODES) g_dinv[i] = rsqrtf((float)g_cursor[i] + 1.0f);
}

// ---------------- tf32 tensor-core GEMM: g_tmp[N,128] = A[N,K] @ W[K,128] ----------------
__device__ __forceinline__ float cvt_tf32(float x) {
    uint32_t u;
    asm("cvt.rna.tf32.f32 %0, %1;" : "=r"(u) : "f"(x));
    return __uint_as_float(u);
}

// 128x128 tile, 256 threads = 8 warps (4 m x 2 n), warp tile 32x64.
// m16n8k8 tf32 mma; As row-major [128][36] (bank-perm 4*gid+tig),
// Bs k-major [32][136] (bank-perm 8*tig+gid). All smem accesses conflict-free.
template <int K, bool USE_H>
__global__ void __launch_bounds__(256, 2) k_gemm_tf32(const float* __restrict__ A,
                                                      const float* __restrict__ W) {
    constexpr int KC = 32;
    __shared__ float As[128][36];
    __shared__ float Bs[KC][136];
    const float* Ain = USE_H ? g_h : A;
    int node0 = blockIdx.x * 128;
    int tid  = threadIdx.x;
    int wid  = tid >> 5, lane = tid & 31;
    int wm   = wid >> 1, wn = wid & 1;
    int rb   = wm * 32,  cb = wn * 64;
    int gid  = lane >> 2, tig = lane & 3;

    float acc[2][8][4];
#pragma unroll
    for (int mi = 0; mi < 2; mi++)
#pragma unroll
        for (int ni = 0; ni < 8; ni++)
#pragma unroll
            for (int c = 0; c < 4; c++) acc[mi][ni][c] = 0.0f;

    for (int kc = 0; kc < K; kc += KC) {
        // stage A: 128 rows x 32 k; idx -> row=idx>>3, kv=(idx&7)*4
#pragma unroll
        for (int t = 0; t < 4; t++) {
            int idx = tid + t * 256;
            int row = idx >> 3, kv = (idx & 7) * 4;
            int gr = node0 + row; if (gr >= N_NODES) gr = N_NODES - 1;
            float4 v = *(const float4*)&Ain[(size_t)gr * K + kc + kv];
            float4 c = make_float4(cvt_tf32(v.x), cvt_tf32(v.y), cvt_tf32(v.z), cvt_tf32(v.w));
            *(float4*)&As[row][kv] = c;
        }
        // stage B: 32 k x 128 cols; idx -> kr=idx>>5, c4=(idx&31)*4
#pragma unroll
        for (int t = 0; t < 4; t++) {
            int idx = tid + t * 256;
            int kr = idx >> 5, c4 = (idx & 31) * 4;
            float4 v = *(const float4*)&W[(size_t)(kc + kr) * 128 + c4];
            float4 c = make_float4(cvt_tf32(v.x), cvt_tf32(v.y), cvt_tf32(v.z), cvt_tf32(v.w));
            *(float4*)&Bs[kr][c4] = c;
        }
        __syncthreads();

#pragma unroll
        for (int k0 = 0; k0 < KC; k0 += 8) {
            uint32_t a[2][4];
#pragma unroll
            for (int mi = 0; mi < 2; mi++) {
                int r0 = rb + mi * 16 + gid;
                a[mi][0] = __float_as_uint(As[r0    ][k0 + tig]);
                a[mi][1] = __float_as_uint(As[r0 + 8][k0 + tig]);
                a[mi][2] = __float_as_uint(As[r0    ][k0 + tig + 4]);
                a[mi][3] = __float_as_uint(As[r0 + 8][k0 + tig + 4]);
            }
#pragma unroll
            for (int ni = 0; ni < 8; ni++) {
                uint32_t b0 = __float_as_uint(Bs[k0 + tig    ][cb + ni * 8 + gid]);
                uint32_t b1 = __float_as_uint(Bs[k0 + tig + 4][cb + ni * 8 + gid]);
#pragma unroll
                for (int mi = 0; mi < 2; mi++) {
                    asm volatile(
                        "mma.sync.aligned.m16n8k8.row.col.f32.tf32.tf32.f32 "
                        "{%0,%1,%2,%3}, {%4,%5,%6,%7}, {%8,%9}, {%0,%1,%2,%3};"
                        : "+f"(acc[mi][ni][0]), "+f"(acc[mi][ni][1]),
                          "+f"(acc[mi][ni][2]), "+f"(acc[mi][ni][3])
                        : "r"(a[mi][0]), "r"(a[mi][1]), "r"(a[mi][2]), "r"(a[mi][3]),
                          "r"(b0), "r"(b1));
                }
            }
        }
        __syncthreads();
    }

    // epilogue: c0,c1 -> (row=gid, col=2*tig), c2,c3 -> row+8
#pragma unroll
    for (int mi = 0; mi < 2; mi++) {
        int r0 = node0 + rb + mi * 16 + gid;
#pragma unroll
        for (int ni = 0; ni < 8; ni++) {
            int c0 = cb + ni * 8 + tig * 2;
            if (r0 < N_NODES)
                *(float2*)&g_tmp[(size_t)r0 * 128 + c0] =
                    make_float2(acc[mi][ni][0], acc[mi][ni][1]);
            if (r0 + 8 < N_NODES)
                *(float2*)&g_tmp[(size_t)(r0 + 8) * 128 + c0] =
                    make_float2(acc[mi][ni][2], acc[mi][ni][3]);
        }
    }
}

// ---------------- aggregation: h[v] = sum_{s->v} norm * xw[s] (+self) + bias ----------------
__device__ __forceinline__ float4 agg_node(int w, int lane, const float* __restrict__ bias) {
    const float4* xw4 = (const float4*)g_tmp;
    float dv = g_dinv[w];
    float sw = dv * dv;

    float4 a = xw4[(size_t)w * 32 + lane];
    float4 acc = make_float4(a.x * sw, a.y * sw, a.z * sw, a.w * sw);

    int cnt = g_cursor[w];
    if (cnt > CAP) cnt = CAP;
    const int* sb = &g_srcbuf[(size_t)w * CAP];
    for (int e = 0; e < cnt; e++) {
        int s = __ldg(&sb[e]);
        float wt = __ldg(&g_dinv[s]) * dv;
        float4 v = xw4[(size_t)s * 32 + lane];
        acc.x += v.x * wt; acc.y += v.y * wt;
        acc.z += v.z * wt; acc.w += v.w * wt;
    }
    float4 b = ((const float4*)bias)[lane];
    acc.x += b.x; acc.y += b.y; acc.z += b.z; acc.w += b.w;
    return acc;
}

__global__ void k_agg_relu(const float* __restrict__ bias) {
    int w = (blockIdx.x * blockDim.x + threadIdx.x) >> 5;
    int lane = threadIdx.x & 31;
    if (w >= N_NODES) return;
    float4 acc = agg_node(w, lane, bias);
    acc.x = fmaxf(acc.x, 0.0f); acc.y = fmaxf(acc.y, 0.0f);
    acc.z = fmaxf(acc.z, 0.0f); acc.w = fmaxf(acc.w, 0.0f);
    ((float4*)g_h)[(size_t)w * 32 + lane] = acc;
}

// layer-2 aggregation fused with the node-classification head
__global__ void k_agg_nodehead(const float* __restrict__ bias,
                               const float* __restrict__ Wc, const float* __restrict__ bc,
                               float* __restrict__ out) {
    int v = (blockIdx.x * blockDim.x + threadIdx.x) >> 5;
    int lane = threadIdx.x & 31;
    if (v >= N_NODES) return;

    float4 hv = agg_node(v, lane, bias);
    ((float4*)g_h)[(size_t)v * 32 + lane] = hv;   // link head needs h

    float r0 = fmaxf(hv.x, 0.0f), r1 = fmaxf(hv.y, 0.0f);
    float r2 = fmaxf(hv.z, 0.0f), r3 = fmaxf(hv.w, 0.0f);
    int k0 = lane * 4;

    float logits[N_CLS];
#pragma unroll
    for (int c = 0; c < N_CLS; c++) {
        float p = r0 * __ldg(&Wc[(k0 + 0) * N_CLS + c])
                + r1 * __ldg(&Wc[(k0 + 1) * N_CLS + c])
                + r2 * __ldg(&Wc[(k0 + 2) * N_CLS + c])
                + r3 * __ldg(&Wc[(k0 + 3) * N_CLS + c]);
#pragma unroll
        for (int o = 16; o > 0; o >>= 1) p += __shfl_xor_sync(0xffffffffu, p, o);
        logits[c] = p + __ldg(&bc[c]);
    }

    float m = logits[0];
#pragma unroll
    for (int c = 1; c < N_CLS; c++) m = fmaxf(m, logits[c]);
    float se = 0.0f;
#pragma unroll
    for (int c = 0; c < N_CLS; c++) se += expf(logits[c] - m);
    float lse = m + logf(se);

    if (lane < N_CLS) {
        float val = logits[0];
#pragma unroll
        for (int c = 1; c < N_CLS; c++) if (lane == c) val = logits[c];
        out[(size_t)v * N_CLS + lane] = val - lse;
    }
}

// ---------------- link head ----------------
__global__ void k_link(const int* __restrict__ ep, const int* __restrict__ en,
                       const float* __restrict__ Wl, const float* __restrict__ bl,
                       float* __restrict__ out) {
    int w = (blockIdx.x * blockDim.x + threadIdx.x) >> 5;
    int lane = threadIdx.x & 31;
    if (w >= N_EP + N_EN) return;

    int s, d;
    float* o;
    if (w < N_EP) {
        s = ep[w]; d = ep[N_EP + w]; o = out + w;
    } else {
        int w2 = w - N_EP;
        s = en[w2]; d = en[N_EN + w2]; o = out + N_EP + w2;
    }

    float4 hs = ((const float4*)g_h)[(size_t)s * 32 + lane];
    float4 hd = ((const float4*)g_h)[(size_t)d * 32 + lane];
    float4 ws = ((const float4*)Wl)[lane];
    float4 wd = ((const float4*)(Wl + 128))[lane];

    float p = hs.x * ws.x + hs.y * ws.y + hs.z * ws.z + hs.w * ws.w
            + hd.x * wd.x + hd.y * wd.y + hd.z * wd.z + hd.w * wd.w;
#pragma unroll
    for (int o2 = 16; o2 > 0; o2 >>= 1) p += __shfl_xor_sync(0xffffffffu, p, o2);

    if (lane == 0) *o = p + bl[0];
}

// ---------------- launch ----------------
extern "C" void kernel_launch(void* const* d_in, const int* in_sizes, int n_in,
                              void* d_out, int out_size) {
    const float* x   = (const float*)d_in[0];
    const int*   ei  = (const int*)d_in[1];
    const int*   ep  = (const int*)d_in[2];
    const int*   en  = (const int*)d_in[3];
    const float* W1  = (const float*)d_in[4];
    const float* b1  = (const float*)d_in[5];
    const float* W2  = (const float*)d_in[6];
    const float* b2  = (const float*)d_in[7];
    const float* Wc  = (const float*)d_in[8];
    const float* bc  = (const float*)d_in[9];
    const float* Wl  = (const float*)d_in[10];
    const float* bl  = (const float*)d_in[11];
    float* out = (float*)d_out;

    // graph preprocessing (cursor doubles as degree count)
    k_zero<<<(N_NODES + 255) / 256, 256>>>();
    k_bucket<<<N_EDGES / 256, 256>>>(ei);
    k_dinv<<<(N_NODES + 255) / 256, 256>>>();

    const int GEMM_GRID = (N_NODES + 127) / 128;

    // layer 1: tmp = x @ W1 ; h = relu(agg(tmp) + b1)
    k_gemm_tf32<IN_CH, false><<<GEMM_GRID, 256>>>(x, W1);
    k_agg_relu<<<N_NODES / 8, 256>>>(b1);

    // layer 2: tmp = h @ W2 ; h = agg(tmp) + b2 ; node head fused
    k_gemm_tf32<HID, true><<<GEMM_GRID, 256>>>(nullptr, W2);
    k_agg_nodehead<<<N_NODES / 8, 256>>>(b2, Wc, bc, out);

    // link head
    k_link<<<(N_EP + N_EN) / 8, 256>>>(ep, en, Wl, bl, out + NODE_OUT_ELEMS);
}

// round 5
// speedup vs baseline: 1.8094x; 1.0069x over previous
#include <cuda_runtime.h>
#include <cstdint>

#define N_NODES 100000
#define N_EDGES 1600000
#define N_EP    200000
#define N_EN    200000
#define IN_CH   256
#define HID     128
#define N_CLS   10
#define CAP     64
#define NODE_OUT_ELEMS (N_NODES * N_CLS)

// ---------------- static device scratch (no allocation allowed) ----------------
__device__ int   g_cursor[N_NODES];                   // degree counts / bucket cursor
__device__ float g_dinv[N_NODES];
__device__ int   g_srcbuf[(size_t)N_NODES * CAP];     // 25.6 MB
__device__ float g_tmp[(size_t)N_NODES * 128];        // 51.2 MB  (x@W buffer)
__device__ float g_h[(size_t)N_NODES * 128];          // 51.2 MB  (aggregated h)

// ---------------- graph preprocessing ----------------
__global__ void k_zero() {
    int i = blockIdx.x * blockDim.x + threadIdx.x;
    if (i < N_NODES) g_cursor[i] = 0;
}

__global__ void k_bucket(const int* __restrict__ ei) {
    int i = blockIdx.x * blockDim.x + threadIdx.x;
    if (i < N_EDGES) {
        int d = ei[N_EDGES + i];
        int slot = atomicAdd(&g_cursor[d], 1);
        if (slot < CAP) g_srcbuf[(size_t)d * CAP + slot] = ei[i];
    }
}

__global__ void k_dinv() {
    int i = blockIdx.x * blockDim.x + threadIdx.x;
    if (i < N_NODES) g_dinv[i] = rsqrtf((float)g_cursor[i] + 1.0f);
}

// ---------------- tf32 tensor-core GEMM: g_tmp[N,128] = A[N,K] @ W[K,128] ----------------
__device__ __forceinline__ float cvt_tf32(float x) {
    uint32_t u;
    asm("cvt.rna.tf32.f32 %0, %1;" : "=r"(u) : "f"(x));
    return __uint_as_float(u);
}

// 128x128 tile, 256 threads = 8 warps (4 m x 2 n), warp tile 32x64.
template <int K, bool USE_H>
__global__ void __launch_bounds__(256, 2) k_gemm_tf32(const float* __restrict__ A,
                                                      const float* __restrict__ W) {
    constexpr int KC = 32;
    __shared__ float As[128][36];
    __shared__ float Bs[KC][136];
    const float* Ain = USE_H ? g_h : A;
    int node0 = blockIdx.x * 128;
    int tid  = threadIdx.x;
    int wid  = tid >> 5, lane = tid & 31;
    int wm   = wid >> 1, wn = wid & 1;
    int rb   = wm * 32,  cb = wn * 64;
    int gid  = lane >> 2, tig = lane & 3;

    float acc[2][8][4];
#pragma unroll
    for (int mi = 0; mi < 2; mi++)
#pragma unroll
        for (int ni = 0; ni < 8; ni++)
#pragma unroll
            for (int c = 0; c < 4; c++) acc[mi][ni][c] = 0.0f;

    for (int kc = 0; kc < K; kc += KC) {
#pragma unroll
        for (int t = 0; t < 4; t++) {
            int idx = tid + t * 256;
            int row = idx >> 3, kv = (idx & 7) * 4;
            int gr = node0 + row; if (gr >= N_NODES) gr = N_NODES - 1;
            float4 v = *(const float4*)&Ain[(size_t)gr * K + kc + kv];
            float4 c = make_float4(cvt_tf32(v.x), cvt_tf32(v.y), cvt_tf32(v.z), cvt_tf32(v.w));
            *(float4*)&As[row][kv] = c;
        }
#pragma unroll
        for (int t = 0; t < 4; t++) {
            int idx = tid + t * 256;
            int kr = idx >> 5, c4 = (idx & 31) * 4;
            float4 v = *(const float4*)&W[(size_t)(kc + kr) * 128 + c4];
            float4 c = make_float4(cvt_tf32(v.x), cvt_tf32(v.y), cvt_tf32(v.z), cvt_tf32(v.w));
            *(float4*)&Bs[kr][c4] = c;
        }
        __syncthreads();

#pragma unroll
        for (int k0 = 0; k0 < KC; k0 += 8) {
            uint32_t a[2][4];
#pragma unroll
            for (int mi = 0; mi < 2; mi++) {
                int r0 = rb + mi * 16 + gid;
                a[mi][0] = __float_as_uint(As[r0    ][k0 + tig]);
                a[mi][1] = __float_as_uint(As[r0 + 8][k0 + tig]);
                a[mi][2] = __float_as_uint(As[r0    ][k0 + tig + 4]);
                a[mi][3] = __float_as_uint(As[r0 + 8][k0 + tig + 4]);
            }
#pragma unroll
            for (int ni = 0; ni < 8; ni++) {
                uint32_t b0 = __float_as_uint(Bs[k0 + tig    ][cb + ni * 8 + gid]);
                uint32_t b1 = __float_as_uint(Bs[k0 + tig + 4][cb + ni * 8 + gid]);
#pragma unroll
                for (int mi = 0; mi < 2; mi++) {
                    asm volatile(
                        "mma.sync.aligned.m16n8k8.row.col.f32.tf32.tf32.f32 "
                        "{%0,%1,%2,%3}, {%4,%5,%6,%7}, {%8,%9}, {%0,%1,%2,%3};"
                        : "+f"(acc[mi][ni][0]), "+f"(acc[mi][ni][1]),
                          "+f"(acc[mi][ni][2]), "+f"(acc[mi][ni][3])
                        : "r"(a[mi][0]), "r"(a[mi][1]), "r"(a[mi][2]), "r"(a[mi][3]),
                          "r"(b0), "r"(b1));
                }
            }
        }
        __syncthreads();
    }

#pragma unroll
    for (int mi = 0; mi < 2; mi++) {
        int r0 = node0 + rb + mi * 16 + gid;
#pragma unroll
        for (int ni = 0; ni < 8; ni++) {
            int c0 = cb + ni * 8 + tig * 2;
            if (r0 < N_NODES)
                *(float2*)&g_tmp[(size_t)r0 * 128 + c0] =
                    make_float2(acc[mi][ni][0], acc[mi][ni][1]);
            if (r0 + 8 < N_NODES)
                *(float2*)&g_tmp[(size_t)(r0 + 8) * 128 + c0] =
                    make_float2(acc[mi][ni][2], acc[mi][ni][3]);
        }
    }
}

// ---------------- aggregation: h[v] = sum_{s->v} norm * xw[s] (+self) + bias ----------------
// One warp per node; lane owns a float4. Edge loop unrolled x4 for MLP.
__device__ __forceinline__ float4 agg_node(int w, int lane, const float* __restrict__ bias) {
    const float4* xw4 = (const float4*)g_tmp;
    float dv = g_dinv[w];
    float sw = dv * dv;

    float4 a = xw4[(size_t)w * 32 + lane];
    float4 acc = make_float4(a.x * sw, a.y * sw, a.z * sw, a.w * sw);

    int cnt = g_cursor[w];
    if (cnt > CAP) cnt = CAP;
    const int* sb = &g_srcbuf[(size_t)w * CAP];

    int e = 0;
    for (; e + 4 <= cnt; e += 4) {
        int s0 = __ldg(&sb[e]), s1 = __ldg(&sb[e + 1]);
        int s2 = __ldg(&sb[e + 2]), s3 = __ldg(&sb[e + 3]);
        float w0 = __ldg(&g_dinv[s0]) * dv, w1 = __ldg(&g_dinv[s1]) * dv;
        float w2 = __ldg(&g_dinv[s2]) * dv, w3 = __ldg(&g_dinv[s3]) * dv;
        float4 v0 = xw4[(size_t)s0 * 32 + lane];
        float4 v1 = xw4[(size_t)s1 * 32 + lane];
        float4 v2 = xw4[(size_t)s2 * 32 + lane];
        float4 v3 = xw4[(size_t)s3 * 32 + lane];
        acc.x += v0.x * w0; acc.y += v0.y * w0; acc.z += v0.z * w0; acc.w += v0.w * w0;
        acc.x += v1.x * w1; acc.y += v1.y * w1; acc.z += v1.z * w1; acc.w += v1.w * w1;
        acc.x += v2.x * w2; acc.y += v2.y * w2; acc.z += v2.z * w2; acc.w += v2.w * w2;
        acc.x += v3.x * w3; acc.y += v3.y * w3; acc.z += v3.z * w3; acc.w += v3.w * w3;
    }
    for (; e < cnt; e++) {
        int s = __ldg(&sb[e]);
        float wt = __ldg(&g_dinv[s]) * dv;
        float4 v = xw4[(size_t)s * 32 + lane];
        acc.x += v.x * wt; acc.y += v.y * wt;
        acc.z += v.z * wt; acc.w += v.w * wt;
    }
    float4 b = ((const float4*)bias)[lane];
    acc.x += b.x; acc.y += b.y; acc.z += b.z; acc.w += b.w;
    return acc;
}

__global__ void k_agg_relu(const float* __restrict__ bias) {
    int w = (blockIdx.x * blockDim.x + threadIdx.x) >> 5;
    int lane = threadIdx.x & 31;
    if (w >= N_NODES) return;
    float4 acc = agg_node(w, lane, bias);
    acc.x = fmaxf(acc.x, 0.0f); acc.y = fmaxf(acc.y, 0.0f);
    acc.z = fmaxf(acc.z, 0.0f); acc.w = fmaxf(acc.w, 0.0f);
    ((float4*)g_h)[(size_t)w * 32 + lane] = acc;
}

// layer-2 aggregation fused with the node-classification head
__global__ void k_agg_nodehead(const float* __restrict__ bias,
                               const float* __restrict__ Wc, const float* __restrict__ bc,
                               float* __restrict__ out) {
    int v = (blockIdx.x * blockDim.x + threadIdx.x) >> 5;
    int lane = threadIdx.x & 31;
    if (v >= N_NODES) return;

    float4 hv = agg_node(v, lane, bias);
    ((float4*)g_h)[(size_t)v * 32 + lane] = hv;   // link head needs h

    float r0 = fmaxf(hv.x, 0.0f), r1 = fmaxf(hv.y, 0.0f);
    float r2 = fmaxf(hv.z, 0.0f), r3 = fmaxf(hv.w, 0.0f);
    int k0 = lane * 4;

    float logits[N_CLS];
#pragma unroll
    for (int c = 0; c < N_CLS; c++) {
        float p = r0 * __ldg(&Wc[(k0 + 0) * N_CLS + c])
                + r1 * __ldg(&Wc[(k0 + 1) * N_CLS + c])
                + r2 * __ldg(&Wc[(k0 + 2) * N_CLS + c])
                + r3 * __ldg(&Wc[(k0 + 3) * N_CLS + c]);
#pragma unroll
        for (int o = 16; o > 0; o >>= 1) p += __shfl_xor_sync(0xffffffffu, p, o);
        logits[c] = p + __ldg(&bc[c]);
    }

    float m = logits[0];
#pragma unroll
    for (int c = 1; c < N_CLS; c++) m = fmaxf(m, logits[c]);
    float se = 0.0f;
#pragma unroll
    for (int c = 0; c < N_CLS; c++) se += expf(logits[c] - m);
    float lse = m + logf(se);

    if (lane < N_CLS) {
        float val = logits[0];
#pragma unroll
        for (int c = 1; c < N_CLS; c++) if (lane == c) val = logits[c];
        out[(size_t)v * N_CLS + lane] = val - lse;
    }
}

// ---------------- link head ----------------
__global__ void k_link(const int* __restrict__ ep, const int* __restrict__ en,
                       const float* __restrict__ Wl, const float* __restrict__ bl,
                       float* __restrict__ out) {
    int w = (blockIdx.x * blockDim.x + threadIdx.x) >> 5;
    int lane = threadIdx.x & 31;
    if (w >= N_EP + N_EN) return;

    int s, d;
    float* o;
    if (w < N_EP) {
        s = ep[w]; d = ep[N_EP + w]; o = out + w;
    } else {
        int w2 = w - N_EP;
        s = en[w2]; d = en[N_EN + w2]; o = out + N_EP + w2;
    }

    float4 hs = ((const float4*)g_h)[(size_t)s * 32 + lane];
    float4 hd = ((const float4*)g_h)[(size_t)d * 32 + lane];
    float4 ws = ((const float4*)Wl)[lane];
    float4 wd = ((const float4*)(Wl + 128))[lane];

    float p = hs.x * ws.x + hs.y * ws.y + hs.z * ws.z + hs.w * ws.w
            + hd.x * wd.x + hd.y * wd.y + hd.z * wd.z + hd.w * wd.w;
#pragma unroll
    for (int o2 = 16; o2 > 0; o2 >>= 1) p += __shfl_xor_sync(0xffffffffu, p, o2);

    if (lane == 0) *o = p + bl[0];
}

// ---------------- launch ----------------
extern "C" void kernel_launch(void* const* d_in, const int* in_sizes, int n_in,
                              void* d_out, int out_size) {
    const float* x   = (const float*)d_in[0];
    const int*   ei  = (const int*)d_in[1];
    const int*   ep  = (const int*)d_in[2];
    const int*   en  = (const int*)d_in[3];
    const float* W1  = (const float*)d_in[4];
    const float* b1  = (const float*)d_in[5];
    const float* W2  = (const float*)d_in[6];
    const float* b2  = (const float*)d_in[7];
    const float* Wc  = (const float*)d_in[8];
    const float* bc  = (const float*)d_in[9];
    const float* Wl  = (const float*)d_in[10];
    const float* bl  = (const float*)d_in[11];
    float* out = (float*)d_out;

    // one-time host resources (streams/events are not device memory)
    static cudaStream_t s_pre = nullptr;
    static cudaEvent_t ev_start = nullptr, ev_pre = nullptr;
    if (s_pre == nullptr) {
        if (cudaStreamCreateWithFlags(&s_pre, cudaStreamNonBlocking) != cudaSuccess)
            s_pre = nullptr;
        else {
            cudaEventCreateWithFlags(&ev_start, cudaEventDisableTiming);
            cudaEventCreateWithFlags(&ev_pre, cudaEventDisableTiming);
        }
    }

    const int GEMM_GRID = (N_NODES + 127) / 128;

    if (s_pre) {
        // fork: preprocessing on side stream, gemm1 on main stream
        cudaEventRecord(ev_start, 0);
        cudaStreamWaitEvent(s_pre, ev_start, 0);
        k_zero<<<(N_NODES + 255) / 256, 256, 0, s_pre>>>();
        k_bucket<<<N_EDGES / 256, 256, 0, s_pre>>>(ei);
        k_dinv<<<(N_NODES + 255) / 256, 256, 0, s_pre>>>();
        cudaEventRecord(ev_pre, s_pre);

        k_gemm_tf32<IN_CH, false><<<GEMM_GRID, 256>>>(x, W1);
        cudaStreamWaitEvent(0, ev_pre, 0);   // join before aggregation
    } else {
        k_zero<<<(N_NODES + 255) / 256, 256>>>();
        k_bucket<<<N_EDGES / 256, 256>>>(ei);
        k_dinv<<<(N_NODES + 255) / 256, 256>>>();
        k_gemm_tf32<IN_CH, false><<<GEMM_GRID, 256>>>(x, W1);
    }

    // layer 1 aggregation
    k_agg_relu<<<N_NODES / 8, 256>>>(b1);

    // layer 2: tmp = h @ W2 ; agg + node head fused
    k_gemm_tf32<HID, true><<<GEMM_GRID, 256>>>(nullptr, W2);
    k_agg_nodehead<<<N_NODES / 8, 256>>>(b2, Wc, bc, out);

    // link head
    k_link<<<(N_EP + N_EN) / 8, 256>>>(ep, en, Wl, bl, out + NODE_OUT_ELEMS);
}

// round 6
// speedup vs baseline: 1.9156x; 1.0587x over previous
#include <cuda_runtime.h>
#include <cuda_fp16.h>
#include <cstdint>

#define N_NODES 100000
#define N_EDGES 1600000
#define N_EP    200000
#define N_EN    200000
#define IN_CH   256
#define HID     128
#define N_CLS   10
#define CAP     64
#define NODE_OUT_ELEMS (N_NODES * N_CLS)

// ---------------- static device scratch (no allocation allowed) ----------------
__device__ int    g_cursor[N_NODES];                  // degree counts / bucket cursor
__device__ float  g_dinv[N_NODES];
__device__ int    g_srcbuf[(size_t)N_NODES * CAP];    // 25.6 MB
__device__ __half g_tmph[(size_t)N_NODES * 128];      // 25.6 MB  (x@W buffer, fp16)
__device__ float  g_h[(size_t)N_NODES * 128];         // 51.2 MB  (aggregated h, fp32)

// ---------------- graph preprocessing ----------------
__global__ void k_zero() {
    int i = blockIdx.x * blockDim.x + threadIdx.x;
    if (i < N_NODES) g_cursor[i] = 0;
}

__global__ void k_bucket(const int* __restrict__ ei) {
    int i = blockIdx.x * blockDim.x + threadIdx.x;
    if (i < N_EDGES) {
        int d = ei[N_EDGES + i];
        int slot = atomicAdd(&g_cursor[d], 1);
        if (slot < CAP) g_srcbuf[(size_t)d * CAP + slot] = ei[i];
    }
}

__global__ void k_dinv() {
    int i = blockIdx.x * blockDim.x + threadIdx.x;
    if (i < N_NODES) g_dinv[i] = rsqrtf((float)g_cursor[i] + 1.0f);
}

// ---------------- tf32 tensor-core GEMM: g_tmph[N,128] = fp16(A[N,K] @ W[K,128]) ----------------
__device__ __forceinline__ float cvt_tf32(float x) {
    uint32_t u;
    asm("cvt.rna.tf32.f32 %0, %1;" : "=r"(u) : "f"(x));
    return __uint_as_float(u);
}

// 128x128 tile, 256 threads = 8 warps (4 m x 2 n), warp tile 32x64.
template <int K, bool USE_H>
__global__ void __launch_bounds__(256, 2) k_gemm_tf32(const float* __restrict__ A,
                                                      const float* __restrict__ W) {
    constexpr int KC = 32;
    __shared__ float As[128][36];
    __shared__ float Bs[KC][136];
    const float* Ain = USE_H ? g_h : A;
    int node0 = blockIdx.x * 128;
    int tid  = threadIdx.x;
    int wid  = tid >> 5, lane = tid & 31;
    int wm   = wid >> 1, wn = wid & 1;
    int rb   = wm * 32,  cb = wn * 64;
    int gid  = lane >> 2, tig = lane & 3;

    float acc[2][8][4];
#pragma unroll
    for (int mi = 0; mi < 2; mi++)
#pragma unroll
        for (int ni = 0; ni < 8; ni++)
#pragma unroll
            for (int c = 0; c < 4; c++) acc[mi][ni][c] = 0.0f;

    for (int kc = 0; kc < K; kc += KC) {
#pragma unroll
        for (int t = 0; t < 4; t++) {
            int idx = tid + t * 256;
            int row = idx >> 3, kv = (idx & 7) * 4;
            int gr = node0 + row; if (gr >= N_NODES) gr = N_NODES - 1;
            float4 v = *(const float4*)&Ain[(size_t)gr * K + kc + kv];
            float4 c = make_float4(cvt_tf32(v.x), cvt_tf32(v.y), cvt_tf32(v.z), cvt_tf32(v.w));
            *(float4*)&As[row][kv] = c;
        }
#pragma unroll
        for (int t = 0; t < 4; t++) {
            int idx = tid + t * 256;
            int kr = idx >> 5, c4 = (idx & 31) * 4;
            float4 v = *(const float4*)&W[(size_t)(kc + kr) * 128 + c4];
            float4 c = make_float4(cvt_tf32(v.x), cvt_tf32(v.y), cvt_tf32(v.z), cvt_tf32(v.w));
            *(float4*)&Bs[kr][c4] = c;
        }
        __syncthreads();

#pragma unroll
        for (int k0 = 0; k0 < KC; k0 += 8) {
            uint32_t a[2][4];
#pragma unroll
            for (int mi = 0; mi < 2; mi++) {
                int r0 = rb + mi * 16 + gid;
                a[mi][0] = __float_as_uint(As[r0    ][k0 + tig]);
                a[mi][1] = __float_as_uint(As[r0 + 8][k0 + tig]);
                a[mi][2] = __float_as_uint(As[r0    ][k0 + tig + 4]);
                a[mi][3] = __float_as_uint(As[r0 + 8][k0 + tig + 4]);
            }
#pragma unroll
            for (int ni = 0; ni < 8; ni++) {
                uint32_t b0 = __float_as_uint(Bs[k0 + tig    ][cb + ni * 8 + gid]);
                uint32_t b1 = __float_as_uint(Bs[k0 + tig + 4][cb + ni * 8 + gid]);
#pragma unroll
                for (int mi = 0; mi < 2; mi++) {
                    asm volatile(
                        "mma.sync.aligned.m16n8k8.row.col.f32.tf32.tf32.f32 "
                        "{%0,%1,%2,%3}, {%4,%5,%6,%7}, {%8,%9}, {%0,%1,%2,%3};"
                        : "+f"(acc[mi][ni][0]), "+f"(acc[mi][ni][1]),
                          "+f"(acc[mi][ni][2]), "+f"(acc[mi][ni][3])
                        : "r"(a[mi][0]), "r"(a[mi][1]), "r"(a[mi][2]), "r"(a[mi][3]),
                          "r"(b0), "r"(b1));
                }
            }
        }
        __syncthreads();
    }

    // epilogue -> fp16: c0,c1 at (row=gid, col=tig*2), c2,c3 at row+8
#pragma unroll
    for (int mi = 0; mi < 2; mi++) {
        int r0 = node0 + rb + mi * 16 + gid;
#pragma unroll
        for (int ni = 0; ni < 8; ni++) {
            int c0 = cb + ni * 8 + tig * 2;
            if (r0 < N_NODES)
                *(__half2*)&g_tmph[(size_t)r0 * 128 + c0] =
                    __floats2half2_rn(acc[mi][ni][0], acc[mi][ni][1]);
            if (r0 + 8 < N_NODES)
                *(__half2*)&g_tmph[(size_t)(r0 + 8) * 128 + c0] =
                    __floats2half2_rn(acc[mi][ni][2], acc[mi][ni][3]);
        }
    }
}

// ---------------- aggregation: h[v] = sum_{s->v} norm * xw[s] (+self) + bias ----------------
// One warp per node; lane owns 4 features (= 2 half2 = one uint2 gather, 8B/lane).
__device__ __forceinline__ float4 h2load(const uint2* __restrict__ p, size_t idx) {
    uint2 u = __ldg(&p[idx]);
    __half2 a = *(__half2*)&u.x, b = *(__half2*)&u.y;
    float2 f0 = __half22float2(a), f1 = __half22float2(b);
    return make_float4(f0.x, f0.y, f1.x, f1.y);
}

__device__ __forceinline__ float4 agg_node(int w, int lane, const float* __restrict__ bias) {
    const uint2* xwh = (const uint2*)g_tmph;   // 32 uint2 per row
    float dv = g_dinv[w];
    float sw = dv * dv;

    float4 a = h2load(xwh, (size_t)w * 32 + lane);
    float4 acc = make_float4(a.x * sw, a.y * sw, a.z * sw, a.w * sw);

    int cnt = g_cursor[w];
    if (cnt > CAP) cnt = CAP;
    const int* sb = &g_srcbuf[(size_t)w * CAP];

    int e = 0;
    for (; e + 4 <= cnt; e += 4) {
        int s0 = __ldg(&sb[e]), s1 = __ldg(&sb[e + 1]);
        int s2 = __ldg(&sb[e + 2]), s3 = __ldg(&sb[e + 3]);
        float w0 = __ldg(&g_dinv[s0]) * dv, w1 = __ldg(&g_dinv[s1]) * dv;
        float w2 = __ldg(&g_dinv[s2]) * dv, w3 = __ldg(&g_dinv[s3]) * dv;
        float4 v0 = h2load(xwh, (size_t)s0 * 32 + lane);
        float4 v1 = h2load(xwh, (size_t)s1 * 32 + lane);
        float4 v2 = h2load(xwh, (size_t)s2 * 32 + lane);
        float4 v3 = h2load(xwh, (size_t)s3 * 32 + lane);
        acc.x += v0.x * w0; acc.y += v0.y * w0; acc.z += v0.z * w0; acc.w += v0.w * w0;
        acc.x += v1.x * w1; acc.y += v1.y * w1; acc.z += v1.z * w1; acc.w += v1.w * w1;
        acc.x += v2.x * w2; acc.y += v2.y * w2; acc.z += v2.z * w2; acc.w += v2.w * w2;
        acc.x += v3.x * w3; acc.y += v3.y * w3; acc.z += v3.z * w3; acc.w += v3.w * w3;
    }
    for (; e < cnt; e++) {
        int s = __ldg(&sb[e]);
        float wt = __ldg(&g_dinv[s]) * dv;
        float4 v = h2load(xwh, (size_t)s * 32 + lane);
        acc.x += v.x * wt; acc.y += v.y * wt;
        acc.z += v.z * wt; acc.w += v.w * wt;
    }
    float4 b = ((const float4*)bias)[lane];
    acc.x += b.x; acc.y += b.y; acc.z += b.z; acc.w += b.w;
    return acc;
}

__global__ void k_agg_relu(const float* __restrict__ bias) {
    int w = (blockIdx.x * blockDim.x + threadIdx.x) >> 5;
    int lane = threadIdx.x & 31;
    if (w >= N_NODES) return;
    float4 acc = agg_node(w, lane, bias);
    acc.x = fmaxf(acc.x, 0.0f); acc.y = fmaxf(acc.y, 0.0f);
    acc.z = fmaxf(acc.z, 0.0f); acc.w = fmaxf(acc.w, 0.0f);
    ((float4*)g_h)[(size_t)w * 32 + lane] = acc;
}

// layer-2 aggregation fused with the node-classification head
__global__ void k_agg_nodehead(const float* __restrict__ bias,
                               const float* __restrict__ Wc, const float* __restrict__ bc,
                               float* __restrict__ out) {
    int v = (blockIdx.x * blockDim.x + threadIdx.x) >> 5;
    int lane = threadIdx.x & 31;
    if (v >= N_NODES) return;

    float4 hv = agg_node(v, lane, bias);
    ((float4*)g_h)[(size_t)v * 32 + lane] = hv;   // link head needs h

    float r0 = fmaxf(hv.x, 0.0f), r1 = fmaxf(hv.y, 0.0f);
    float r2 = fmaxf(hv.z, 0.0f), r3 = fmaxf(hv.w, 0.0f);
    int k0 = lane * 4;

    float logits[N_CLS];
#pragma unroll
    for (int c = 0; c < N_CLS; c++) {
        float p = r0 * __ldg(&Wc[(k0 + 0) * N_CLS + c])
                + r1 * __ldg(&Wc[(k0 + 1) * N_CLS + c])
                + r2 * __ldg(&Wc[(k0 + 2) * N_CLS + c])
                + r3 * __ldg(&Wc[(k0 + 3) * N_CLS + c]);
#pragma unroll
        for (int o = 16; o > 0; o >>= 1) p += __shfl_xor_sync(0xffffffffu, p, o);
        logits[c] = p + __ldg(&bc[c]);
    }

    float m = logits[0];
#pragma unroll
    for (int c = 1; c < N_CLS; c++) m = fmaxf(m, logits[c]);
    float se = 0.0f;
#pragma unroll
    for (int c = 0; c < N_CLS; c++) se += expf(logits[c] - m);
    float lse = m + logf(se);

    if (lane < N_CLS) {
        float val = logits[0];
#pragma unroll
        for (int c = 1; c < N_CLS; c++) if (lane == c) val = logits[c];
        out[(size_t)v * N_CLS + lane] = val - lse;
    }
}

// ---------------- link head ----------------
__global__ void k_link(const int* __restrict__ ep, const int* __restrict__ en,
                       const float* __restrict__ Wl, const float* __restrict__ bl,
                       float* __restrict__ out) {
    int w = (blockIdx.x * blockDim.x + threadIdx.x) >> 5;
    int lane = threadIdx.x & 31;
    if (w >= N_EP + N_EN) return;

    int s, d;
    float* o;
    if (w < N_EP) {
        s = ep[w]; d = ep[N_EP + w]; o = out + w;
    } else {
        int w2 = w - N_EP;
        s = en[w2]; d = en[N_EN + w2]; o = out + N_EP + w2;
    }

    float4 hs = ((const float4*)g_h)[(size_t)s * 32 + lane];
    float4 hd = ((const float4*)g_h)[(size_t)d * 32 + lane];
    float4 ws = ((const float4*)Wl)[lane];
    float4 wd = ((const float4*)(Wl + 128))[lane];

    float p = hs.x * ws.x + hs.y * ws.y + hs.z * ws.z + hs.w * ws.w
            + hd.x * wd.x + hd.y * wd.y + hd.z * wd.z + hd.w * wd.w;
#pragma unroll
    for (int o2 = 16; o2 > 0; o2 >>= 1) p += __shfl_xor_sync(0xffffffffu, p, o2);

    if (lane == 0) *o = p + bl[0];
}

// ---------------- launch ----------------
extern "C" void kernel_launch(void* const* d_in, const int* in_sizes, int n_in,
                              void* d_out, int out_size) {
    const float* x   = (const float*)d_in[0];
    const int*   ei  = (const int*)d_in[1];
    const int*   ep  = (const int*)d_in[2];
    const int*   en  = (const int*)d_in[3];
    const float* W1  = (const float*)d_in[4];
    const float* b1  = (const float*)d_in[5];
    const float* W2  = (const float*)d_in[6];
    const float* b2  = (const float*)d_in[7];
    const float* Wc  = (const float*)d_in[8];
    const float* bc  = (const float*)d_in[9];
    const float* Wl  = (const float*)d_in[10];
    const float* bl  = (const float*)d_in[11];
    float* out = (float*)d_out;

    const int GEMM_GRID = (N_NODES + 127) / 128;

    // graph preprocessing (cursor doubles as degree count)
    k_zero<<<(N_NODES + 255) / 256, 256>>>();
    k_bucket<<<N_EDGES / 256, 256>>>(ei);
    k_dinv<<<(N_NODES + 255) / 256, 256>>>();

    // layer 1: tmph = fp16(x @ W1) ; h = relu(agg(tmph) + b1)
    k_gemm_tf32<IN_CH, false><<<GEMM_GRID, 256>>>(x, W1);
    k_agg_relu<<<N_NODES / 8, 256>>>(b1);

    // layer 2: tmph = fp16(h @ W2) ; agg + node head fused
    k_gemm_tf32<HID, true><<<GEMM_GRID, 256>>>(nullptr, W2);
    k_agg_nodehead<<<N_NODES / 8, 256>>>(b2, Wc, bc, out);

    // link head
    k_link<<<(N_EP + N_EN) / 8, 256>>>(ep, en, Wl, bl, out + NODE_OUT_ELEMS);
}

// round 9
// speedup vs baseline: 2.0270x; 1.0581x over previous
#include <cuda_runtime.h>
#include <cuda_fp16.h>
#include <cstdint>

#define N_NODES 100000
#define N_EDGES 1600000
#define N_EP    200000
#define N_EN    200000
#define IN_CH   256
#define HID     128
#define N_CLS   10
#define CAP     64
#define NODE_OUT_ELEMS (N_NODES * N_CLS)

// ---------------- static device scratch (no allocation allowed) ----------------
__device__ int    g_cursor[N_NODES];                  // degree counts / bucket cursor
__device__ float  g_dinv[N_NODES];
__device__ int    g_srcbuf[(size_t)N_NODES * CAP];    // 25.6 MB
__device__ __half g_tmph[(size_t)N_NODES * 128];      // 25.6 MB  (x@W buffer, fp16)
__device__ float  g_h[(size_t)N_NODES * 128];         // 51.2 MB  (agg1 output, fp32)
__device__ __half g_hh[(size_t)N_NODES * 128];        // 25.6 MB  (agg2 output, fp16)

// ---------------- graph preprocessing ----------------
__global__ void k_zero() {
    int i = blockIdx.x * blockDim.x + threadIdx.x;
    if (i < N_NODES) g_cursor[i] = 0;
}

__global__ void k_bucket(const int* __restrict__ ei) {
    int i = blockIdx.x * blockDim.x + threadIdx.x;
    if (i < N_EDGES) {
        int d = ei[N_EDGES + i];
        int slot = atomicAdd(&g_cursor[d], 1);
        if (slot < CAP) g_srcbuf[(size_t)d * CAP + slot] = ei[i];
    }
}

__global__ void k_dinv() {
    int i = blockIdx.x * blockDim.x + threadIdx.x;
    if (i < N_NODES) g_dinv[i] = rsqrtf((float)g_cursor[i] + 1.0f);
}

// ---------------- tf32 tensor-core GEMM: g_tmph[N,128] = fp16(A[N,K] @ W[K,128]) ----------------
__device__ __forceinline__ float cvt_tf32(float x) {
    uint32_t u;
    asm("cvt.rna.tf32.f32 %0, %1;" : "=r"(u) : "f"(x));
    return __uint_as_float(u);
}

template <int K, bool USE_H>
__global__ void __launch_bounds__(256, 2) k_gemm_tf32(const float* __restrict__ A,
                                                      const float* __restrict__ W) {
    constexpr int KC = 32;
    __shared__ float As[128][36];
    __shared__ float Bs[KC][136];
    const float* Ain = USE_H ? g_h : A;
    int node0 = blockIdx.x * 128;
    int tid  = threadIdx.x;
    int wid  = tid >> 5, lane = tid & 31;
    int wm   = wid >> 1, wn = wid & 1;
    int rb   = wm * 32,  cb = wn * 64;
    int gid  = lane >> 2, tig = lane & 3;

    float acc[2][8][4];
#pragma unroll
    for (int mi = 0; mi < 2; mi++)
#pragma unroll
        for (int ni = 0; ni < 8; ni++)
#pragma unroll
            for (int c = 0; c < 4; c++) acc[mi][ni][c] = 0.0f;

    for (int kc = 0; kc < K; kc += KC) {
#pragma unroll
        for (int t = 0; t < 4; t++) {
            int idx = tid + t * 256;
            int row = idx >> 3, kv = (idx & 7) * 4;
            int gr = node0 + row; if (gr >= N_NODES) gr = N_NODES - 1;
            float4 v = *(const float4*)&Ain[(size_t)gr * K + kc + kv];
            float4 c = make_float4(cvt_tf32(v.x), cvt_tf32(v.y), cvt_tf32(v.z), cvt_tf32(v.w));
            *(float4*)&As[row][kv] = c;
        }
#pragma unroll
        for (int t = 0; t < 4; t++) {
            int idx = tid + t * 256;
            int kr = idx >> 5, c4 = (idx & 31) * 4;
            float4 v = *(const float4*)&W[(size_t)(kc + kr) * 128 + c4];
            float4 c = make_float4(cvt_tf32(v.x), cvt_tf32(v.y), cvt_tf32(v.z), cvt_tf32(v.w));
            *(float4*)&Bs[kr][c4] = c;
        }
        __syncthreads();

#pragma unroll
        for (int k0 = 0; k0 < KC; k0 += 8) {
            uint32_t a[2][4];
#pragma unroll
            for (int mi = 0; mi < 2; mi++) {
                int r0 = rb + mi * 16 + gid;
                a[mi][0] = __float_as_uint(As[r0    ][k0 + tig]);
                a[mi][1] = __float_as_uint(As[r0 + 8][k0 + tig]);
                a[mi][2] = __float_as_uint(As[r0    ][k0 + tig + 4]);
                a[mi][3] = __float_as_uint(As[r0 + 8][k0 + tig + 4]);
            }
#pragma unroll
            for (int ni = 0; ni < 8; ni++) {
                uint32_t b0 = __float_as_uint(Bs[k0 + tig    ][cb + ni * 8 + gid]);
                uint32_t b1 = __float_as_uint(Bs[k0 + tig + 4][cb + ni * 8 + gid]);
#pragma unroll
                for (int mi = 0; mi < 2; mi++) {
                    asm volatile(
                        "mma.sync.aligned.m16n8k8.row.col.f32.tf32.tf32.f32 "
                        "{%0,%1,%2,%3}, {%4,%5,%6,%7}, {%8,%9}, {%0,%1,%2,%3};"
                        : "+f"(acc[mi][ni][0]), "+f"(acc[mi][ni][1]),
                          "+f"(acc[mi][ni][2]), "+f"(acc[mi][ni][3])
                        : "r"(a[mi][0]), "r"(a[mi][1]), "r"(a[mi][2]), "r"(a[mi][3]),
                          "r"(b0), "r"(b1));
                }
            }
        }
        __syncthreads();
    }

#pragma unroll
    for (int mi = 0; mi < 2; mi++) {
        int r0 = node0 + rb + mi * 16 + gid;
#pragma unroll
        for (int ni = 0; ni < 8; ni++) {
            int c0 = cb + ni * 8 + tig * 2;
            if (r0 < N_NODES)
                *(__half2*)&g_tmph[(size_t)r0 * 128 + c0] =
                    __floats2half2_rn(acc[mi][ni][0], acc[mi][ni][1]);
            if (r0 + 8 < N_NODES)
                *(__half2*)&g_tmph[(size_t)(r0 + 8) * 128 + c0] =
                    __floats2half2_rn(acc[mi][ni][2], acc[mi][ni][3]);
        }
    }
}

// ---------------- aggregation: half-warp per node, 2 nodes per warp ----------------
// Lane sl (0..15) owns 8 features = one uint4 (16B) of the 256B fp16 row.
__device__ __forceinline__ void fma8(uint4 u, float wt, float acc[8]) {
    __half2 h0 = *(__half2*)&u.x, h1 = *(__half2*)&u.y;
    __half2 h2 = *(__half2*)&u.z, h3 = *(__half2*)&u.w;
    float2 f0 = __half22float2(h0), f1 = __half22float2(h1);
    float2 f2 = __half22float2(h2), f3 = __half22float2(h3);
    acc[0] += f0.x * wt; acc[1] += f0.y * wt; acc[2] += f1.x * wt; acc[3] += f1.y * wt;
    acc[4] += f2.x * wt; acc[5] += f2.y * wt; acc[6] += f3.x * wt; acc[7] += f3.y * wt;
}

// nd: node for this half-warp; sl: 0..15. Returns 8 accumulated features (bias added).
__device__ __forceinline__ void agg_node8(int nd, int sl, const float* __restrict__ bias,
                                          float acc[8]) {
    const uint4* xwh = (const uint4*)g_tmph;   // 16 uint4 per row
    float dv = g_dinv[nd];

    uint4 sv = __ldg(&xwh[(size_t)nd * 16 + sl]);
#pragma unroll
    for (int j = 0; j < 8; j++) acc[j] = 0.0f;
    fma8(sv, dv * dv, acc);

    int cnt = g_cursor[nd];
    if (cnt > CAP) cnt = CAP;
    int cnt_other = __shfl_xor_sync(0xffffffffu, cnt, 16);
    int cntmax = cnt > cnt_other ? cnt : cnt_other;
    const int* sb = &g_srcbuf[(size_t)nd * CAP];

    int e = 0;
    for (; e + 4 <= cntmax; e += 4) {
        int   s[4]; float wt[4]; uint4 v[4];
#pragma unroll
        for (int i = 0; i < 4; i++) {
            bool ok = (e + i) < cnt;
            s[i]  = ok ? __ldg(&sb[e + i]) : nd;
            wt[i] = ok ? __ldg(&g_dinv[s[i]]) * dv : 0.0f;
        }
#pragma unroll
        for (int i = 0; i < 4; i++) v[i] = __ldg(&xwh[(size_t)s[i] * 16 + sl]);
#pragma unroll
        for (int i = 0; i < 4; i++) fma8(v[i], wt[i], acc);
    }
    for (; e < cntmax; e++) {
        bool ok = e < cnt;
        int s = ok ? __ldg(&sb[e]) : nd;
        float wt = ok ? __ldg(&g_dinv[s]) * dv : 0.0f;
        uint4 v = __ldg(&xwh[(size_t)s * 16 + sl]);
        fma8(v, wt, acc);
    }

    float4 b0 = *(const float4*)&bias[sl * 8];
    float4 b1 = *(const float4*)&bias[sl * 8 + 4];
    acc[0] += b0.x; acc[1] += b0.y; acc[2] += b0.z; acc[3] += b0.w;
    acc[4] += b1.x; acc[5] += b1.y; acc[6] += b1.z; acc[7] += b1.w;
}

// layer-1: h = relu(agg + b1), stored fp32 (gemm2 input)
__global__ void k_agg_relu(const float* __restrict__ bias) {
    int gw = (blockIdx.x * blockDim.x + threadIdx.x) >> 5;   // warp id
    int lane = threadIdx.x & 31;
    int nd = 2 * gw + (lane >> 4);
    int sl = lane & 15;
    if (nd >= N_NODES) return;

    float acc[8];
    agg_node8(nd, sl, bias, acc);
#pragma unroll
    for (int j = 0; j < 8; j++) acc[j] = fmaxf(acc[j], 0.0f);
    *(float4*)&g_h[(size_t)nd * 128 + sl * 8] = make_float4(acc[0], acc[1], acc[2], acc[3]);
    *(float4*)&g_h[(size_t)nd * 128 + sl * 8 + 4] = make_float4(acc[4], acc[5], acc[6], acc[7]);
}

// layer-2 aggregation + node head; h stored fp16 (link head input only)
__global__ void k_agg_nodehead(const float* __restrict__ bias,
                               const float* __restrict__ Wc, const float* __restrict__ bc,
                               float* __restrict__ out) {
    int gw = (blockIdx.x * blockDim.x + threadIdx.x) >> 5;
    int lane = threadIdx.x & 31;
    int nd = 2 * gw + (lane >> 4);
    int sl = lane & 15;
    if (nd >= N_NODES) return;

    float hv[8];
    agg_node8(nd, sl, bias, hv);

    // store fp16 h for link head
    uint4 packed;
    {
        __half2 p0 = __floats2half2_rn(hv[0], hv[1]);
        __half2 p1 = __floats2half2_rn(hv[2], hv[3]);
        __half2 p2 = __floats2half2_rn(hv[4], hv[5]);
        __half2 p3 = __floats2half2_rn(hv[6], hv[7]);
        packed.x = *(uint32_t*)&p0; packed.y = *(uint32_t*)&p1;
        packed.z = *(uint32_t*)&p2; packed.w = *(uint32_t*)&p3;
    }
    *(uint4*)&g_hh[(size_t)nd * 128 + sl * 8] = packed;

    // node head: logits over relu(h)
    float r[8];
#pragma unroll
    for (int j = 0; j < 8; j++) r[j] = fmaxf(hv[j], 0.0f);
    int k0 = sl * 8;

    float logits[N_CLS];
#pragma unroll
    for (int c = 0; c < N_CLS; c++) {
        float p = 0.0f;
#pragma unroll
        for (int j = 0; j < 8; j++) p += r[j] * __ldg(&Wc[(k0 + j) * N_CLS + c]);
#pragma unroll
        for (int o = 8; o > 0; o >>= 1) p += __shfl_xor_sync(0xffffffffu, p, o);
        logits[c] = p + __ldg(&bc[c]);
    }

    float m = logits[0];
#pragma unroll
    for (int c = 1; c < N_CLS; c++) m = fmaxf(m, logits[c]);
    float se = 0.0f;
#pragma unroll
    for (int c = 0; c < N_CLS; c++) se += expf(logits[c] - m);
    float lse = m + logf(se);

    if (sl < N_CLS) {
        float val = logits[0];
#pragma unroll
        for (int c = 1; c < N_CLS; c++) if (sl == c) val = logits[c];
        out[(size_t)nd * N_CLS + sl] = val - lse;
    }
}

// ---------------- link head: 2 edges per warp, fp16 h gathers ----------------
__global__ void k_link(const int* __restrict__ ep, const int* __restrict__ en,
                       const float* __restrict__ Wl, const float* __restrict__ bl,
                       float* __restrict__ out) {
    int gw = (blockIdx.x * blockDim.x + threadIdx.x) >> 5;
    int lane = threadIdx.x & 31;
    int eidx = 2 * gw + (lane >> 4);
    int sl = lane & 15;
    if (eidx >= N_EP + N_EN) return;

    int s, d;
    float* o;
    if (eidx < N_EP) {
        s = ep[eidx]; d = ep[N_EP + eidx]; o = out + eidx;
    } else {
        int e2 = eidx - N_EP;
        s = en[e2]; d = en[N_EN + e2]; o = out + N_EP + e2;
    }

    const uint4* xh = (const uint4*)g_hh;
    uint4 us = __ldg(&xh[(size_t)s * 16 + sl]);
    uint4 ud = __ldg(&xh[(size_t)d * 16 + sl]);

    float hs[8] = {0,0,0,0,0,0,0,0}, hd[8] = {0,0,0,0,0,0,0,0};
    fma8(us, 1.0f, hs);
    fma8(ud, 1.0f, hd);

    float4 w0 = *(const float4*)&Wl[sl * 8];
    float4 w1 = *(const float4*)&Wl[sl * 8 + 4];
    float4 w2 = *(const float4*)&Wl[128 + sl * 8];
    float4 w3 = *(const float4*)&Wl[128 + sl * 8 + 4];

    float p = hs[0] * w0.x + hs[1] * w0.y + hs[2] * w0.z + hs[3] * w0.w
            + hs[4] * w1.x + hs[5] * w1.y + hs[6] * w1.z + hs[7] * w1.w
            + hd[0] * w2.x + hd[1] * w2.y + hd[2] * w2.z + hd[3] * w2.w
            + hd[4] * w3.x + hd[5] * w3.y + hd[6] * w3.z + hd[7] * w3.w;
#pragma unroll
    for (int o2 = 8; o2 > 0; o2 >>= 1) p += __shfl_xor_sync(0xffffffffu, p, o2);

    if (sl == 0) *o = p + bl[0];
}

// ---------------- launch ----------------
extern "C" void kernel_launch(void* const* d_in, const int* in_sizes, int n_in,
                              void* d_out, int out_size) {
    const float* x   = (const float*)d_in[0];
    const int*   ei  = (const int*)d_in[1];
    const int*   ep  = (const int*)d_in[2];
    const int*   en  = (const int*)d_in[3];
    const float* W1  = (const float*)d_in[4];
    const float* b1  = (const float*)d_in[5];
    const float* W2  = (const float*)d_in[6];
    const float* b2  = (const float*)d_in[7];
    const float* Wc  = (const float*)d_in[8];
    const float* bc  = (const float*)d_in[9];
    const float* Wl  = (const float*)d_in[10];
    const float* bl  = (const float*)d_in[11];
    float* out = (float*)d_out;

    const int GEMM_GRID = (N_NODES + 127) / 128;
    const int AGG_GRID  = (N_NODES / 2 + 7) / 8;          // 2 nodes/warp, 8 warps/block
    const int LINK_GRID = ((N_EP + N_EN) / 2 + 7) / 8;    // 2 edges/warp

    // graph preprocessing (cursor doubles as degree count)
    k_zero<<<(N_NODES + 255) / 256, 256>>>();
    k_bucket<<<N_EDGES / 256, 256>>>(ei);
    k_dinv<<<(N_NODES + 255) / 256, 256>>>();

    // layer 1: tmph = fp16(x @ W1) ; h = relu(agg(tmph) + b1)  (fp32)
    k_gemm_tf32<IN_CH, false><<<GEMM_GRID, 256>>>(x, W1);
    k_agg_relu<<<AGG_GRID, 256>>>(b1);

    // layer 2: tmph = fp16(h @ W2) ; agg + node head fused, h stored fp16
    k_gemm_tf32<HID, true><<<GEMM_GRID, 256>>>(nullptr, W2);
    k_agg_nodehead<<<AGG_GRID, 256>>>(b2, Wc, bc, out);

    // link head
    k_link<<<LINK_GRID, 256>>>(ep, en, Wl, bl, out + NODE_OUT_ELEMS);
}

// round 10
// speedup vs baseline: 2.0807x; 1.0265x over previous
#include <cuda_runtime.h>
#include <cuda_fp16.h>
#include <cstdint>

#define N_NODES 100000
#define N_EDGES 1600000
#define N_EP    200000
#define N_EN    200000
#define IN_CH   256
#define HID     128
#define N_CLS   10
#define CAP     64
#define NODE_OUT_ELEMS (N_NODES * N_CLS)

// ---------------- static device scratch (no allocation allowed) ----------------
__device__ int    g_cursor[N_NODES];                  // degree counts / bucket cursor
__device__ float  g_dinv[N_NODES];
__device__ int    g_srcbuf[(size_t)N_NODES * CAP];    // 25.6 MB
__device__ __half g_tmph[(size_t)N_NODES * 128];      // 25.6 MB  (x@W buffer, fp16)
__device__ float  g_h[(size_t)N_NODES * 128];         // 51.2 MB  (agg1 output, fp32)
__device__ __half g_hh[(size_t)N_NODES * 128];        // 25.6 MB  (agg2 output, fp16)

// ---------------- graph preprocessing ----------------
__global__ void k_zero() {
    int i = blockIdx.x * blockDim.x + threadIdx.x;
    if (i < N_NODES) g_cursor[i] = 0;
}

__global__ void k_bucket(const int* __restrict__ ei) {
    int i = blockIdx.x * blockDim.x + threadIdx.x;
    if (i < N_EDGES) {
        int d = ei[N_EDGES + i];
        int slot = atomicAdd(&g_cursor[d], 1);
        if (slot < CAP) g_srcbuf[(size_t)d * CAP + slot] = ei[i];
    }
}

__global__ void k_dinv() {
    int i = blockIdx.x * blockDim.x + threadIdx.x;
    if (i < N_NODES) g_dinv[i] = rsqrtf((float)g_cursor[i] + 1.0f);
}

// ---------------- tf32 tensor-core GEMM: g_tmph[N,128] = fp16(A[N,K] @ W[K,128]) ----------------
__device__ __forceinline__ float cvt_tf32(float x) {
    uint32_t u;
    asm("cvt.rna.tf32.f32 %0, %1;" : "=r"(u) : "f"(x));
    return __uint_as_float(u);
}

template <int K, bool USE_H>
__global__ void __launch_bounds__(256, 2) k_gemm_tf32(const float* __restrict__ A,
                                                      const float* __restrict__ W) {
    constexpr int KC = 32;
    __shared__ float As[128][36];
    __shared__ float Bs[KC][136];
    const float* Ain = USE_H ? g_h : A;
    int node0 = blockIdx.x * 128;
    int tid  = threadIdx.x;
    int wid  = tid >> 5, lane = tid & 31;
    int wm   = wid >> 1, wn = wid & 1;
    int rb   = wm * 32,  cb = wn * 64;
    int gid  = lane >> 2, tig = lane & 3;

    float acc[2][8][4];
#pragma unroll
    for (int mi = 0; mi < 2; mi++)
#pragma unroll
        for (int ni = 0; ni < 8; ni++)
#pragma unroll
            for (int c = 0; c < 4; c++) acc[mi][ni][c] = 0.0f;

    for (int kc = 0; kc < K; kc += KC) {
#pragma unroll
        for (int t = 0; t < 4; t++) {
            int idx = tid + t * 256;
            int row = idx >> 3, kv = (idx & 7) * 4;
            int gr = node0 + row; if (gr >= N_NODES) gr = N_NODES - 1;
            float4 v = *(const float4*)&Ain[(size_t)gr * K + kc + kv];
            float4 c = make_float4(cvt_tf32(v.x), cvt_tf32(v.y), cvt_tf32(v.z), cvt_tf32(v.w));
            *(float4*)&As[row][kv] = c;
        }
#pragma unroll
        for (int t = 0; t < 4; t++) {
            int idx = tid + t * 256;
            int kr = idx >> 5, c4 = (idx & 31) * 4;
            float4 v = *(const float4*)&W[(size_t)(kc + kr) * 128 + c4];
            float4 c = make_float4(cvt_tf32(v.x), cvt_tf32(v.y), cvt_tf32(v.z), cvt_tf32(v.w));
            *(float4*)&Bs[kr][c4] = c;
        }
        __syncthreads();

#pragma unroll
        for (int k0 = 0; k0 < KC; k0 += 8) {
            uint32_t a[2][4];
#pragma unroll
            for (int mi = 0; mi < 2; mi++) {
                int r0 = rb + mi * 16 + gid;
                a[mi][0] = __float_as_uint(As[r0    ][k0 + tig]);
                a[mi][1] = __float_as_uint(As[r0 + 8][k0 + tig]);
                a[mi][2] = __float_as_uint(As[r0    ][k0 + tig + 4]);
                a[mi][3] = __float_as_uint(As[r0 + 8][k0 + tig + 4]);
            }
#pragma unroll
            for (int ni = 0; ni < 8; ni++) {
                uint32_t b0 = __float_as_uint(Bs[k0 + tig    ][cb + ni * 8 + gid]);
                uint32_t b1 = __float_as_uint(Bs[k0 + tig + 4][cb + ni * 8 + gid]);
#pragma unroll
                for (int mi = 0; mi < 2; mi++) {
                    asm volatile(
                        "mma.sync.aligned.m16n8k8.row.col.f32.tf32.tf32.f32 "
                        "{%0,%1,%2,%3}, {%4,%5,%6,%7}, {%8,%9}, {%0,%1,%2,%3};"
                        : "+f"(acc[mi][ni][0]), "+f"(acc[mi][ni][1]),
                          "+f"(acc[mi][ni][2]), "+f"(acc[mi][ni][3])
                        : "r"(a[mi][0]), "r"(a[mi][1]), "r"(a[mi][2]), "r"(a[mi][3]),
                          "r"(b0), "r"(b1));
                }
            }
        }
        __syncthreads();
    }

#pragma unroll
    for (int mi = 0; mi < 2; mi++) {
        int r0 = node0 + rb + mi * 16 + gid;
#pragma unroll
        for (int ni = 0; ni < 8; ni++) {
            int c0 = cb + ni * 8 + tig * 2;
            if (r0 < N_NODES)
                *(__half2*)&g_tmph[(size_t)r0 * 128 + c0] =
                    __floats2half2_rn(acc[mi][ni][0], acc[mi][ni][1]);
            if (r0 + 8 < N_NODES)
                *(__half2*)&g_tmph[(size_t)(r0 + 8) * 128 + c0] =
                    __floats2half2_rn(acc[mi][ni][2], acc[mi][ni][3]);
        }
    }
}

// ---------------- aggregation with block-staged (src, weight) pairs ----------------
// Block = 256 threads = 8 warps; 16 nodes per block (half-warp per node).
// Phase 1: cooperatively stage all (src, dinv[src]*dv) pairs to smem (block-wide MLP).
// Phase 2: gather loop = LDS.64 pair + independent LDG.128 row loads only.
__device__ __forceinline__ void fma8(uint4 u, float wt, float acc[8]) {
    __half2 h0 = *(__half2*)&u.x, h1 = *(__half2*)&u.y;
    __half2 h2 = *(__half2*)&u.z, h3 = *(__half2*)&u.w;
    float2 f0 = __half22float2(h0), f1 = __half22float2(h1);
    float2 f2 = __half22float2(h2), f3 = __half22float2(h3);
    acc[0] += f0.x * wt; acc[1] += f0.y * wt; acc[2] += f1.x * wt; acc[3] += f1.y * wt;
    acc[4] += f2.x * wt; acc[5] += f2.y * wt; acc[6] += f3.x * wt; acc[7] += f3.y * wt;
}

struct SW { int s; float w; };

// Shared staging + per-node gather. Returns acc for node nd = nb + nloc, lane sl (0..15).
template <typename EPILOG>
__device__ __forceinline__ void agg_block(const float* __restrict__ bias, EPILOG epi) {
    __shared__ SW    pairs[16][CAP];     // 8 KB
    __shared__ int   scnt[16];
    __shared__ float sdv[16];

    int tid = threadIdx.x;
    int nb = blockIdx.x * 16;

    if (tid < 16) {
        int c = g_cursor[nb + tid];
        scnt[tid] = c > CAP ? CAP : c;
        sdv[tid] = g_dinv[nb + tid];
    }
    __syncthreads();

    // stage pairs: 16 nodes x 64 slots = 1024 entries, 4 per thread
#pragma unroll
    for (int j = 0; j < 4; j++) {
        int i = tid + j * 256;
        int n = i >> 6, e = i & 63;
        int s = nb + n;
        float w = 0.0f;
        if (e < scnt[n]) {
            s = __ldg(&g_srcbuf[(size_t)(nb + n) * CAP + e]);
            w = __ldg(&g_dinv[s]) * sdv[n];
        }
        pairs[n][e].s = s;
        pairs[n][e].w = w;
    }
    __syncthreads();

    int lane = tid & 31;
    int nloc = 2 * ((tid >> 5)) + (lane >> 4);   // local node 0..15
    int sl = lane & 15;
    int nd = nb + nloc;

    const uint4* xwh = (const uint4*)g_tmph;
    float dv = sdv[nloc];
    float acc[8];
#pragma unroll
    for (int j = 0; j < 8; j++) acc[j] = 0.0f;

    // self term
    fma8(__ldg(&xwh[(size_t)nd * 16 + sl]), dv * dv, acc);

    int cnt = scnt[nloc];
    int cnt_other = __shfl_xor_sync(0xffffffffu, cnt, 16);
    int cntmax = cnt > cnt_other ? cnt : cnt_other;
    cntmax = (cntmax + 3) & ~3;                   // round up; extra entries have w=0

    for (int e = 0; e < cntmax; e += 4) {
        SW p0 = pairs[nloc][e];
        SW p1 = pairs[nloc][e + 1];
        SW p2 = pairs[nloc][e + 2];
        SW p3 = pairs[nloc][e + 3];
        uint4 v0 = __ldg(&xwh[(size_t)p0.s * 16 + sl]);
        uint4 v1 = __ldg(&xwh[(size_t)p1.s * 16 + sl]);
        uint4 v2 = __ldg(&xwh[(size_t)p2.s * 16 + sl]);
        uint4 v3 = __ldg(&xwh[(size_t)p3.s * 16 + sl]);
        fma8(v0, p0.w, acc);
        fma8(v1, p1.w, acc);
        fma8(v2, p2.w, acc);
        fma8(v3, p3.w, acc);
    }

    float4 b0 = *(const float4*)&bias[sl * 8];
    float4 b1 = *(const float4*)&bias[sl * 8 + 4];
    acc[0] += b0.x; acc[1] += b0.y; acc[2] += b0.z; acc[3] += b0.w;
    acc[4] += b1.x; acc[5] += b1.y; acc[6] += b1.z; acc[7] += b1.w;

    epi(nd, sl, acc);
}

// layer-1: h = relu(agg + b1), stored fp32 (gemm2 input)
__global__ void __launch_bounds__(256) k_agg_relu(const float* __restrict__ bias) {
    agg_block(bias, [](int nd, int sl, float acc[8]) {
#pragma unroll
        for (int j = 0; j < 8; j++) acc[j] = fmaxf(acc[j], 0.0f);
        *(float4*)&g_h[(size_t)nd * 128 + sl * 8] = make_float4(acc[0], acc[1], acc[2], acc[3]);
        *(float4*)&g_h[(size_t)nd * 128 + sl * 8 + 4] = make_float4(acc[4], acc[5], acc[6], acc[7]);
    });
}

// layer-2 aggregation + node head; h stored fp16 (link head input only)
__global__ void __launch_bounds__(256) k_agg_nodehead(const float* __restrict__ bias,
                               const float* __restrict__ Wc, const float* __restrict__ bc,
                               float* __restrict__ out) {
    agg_block(bias, [Wc, bc, out](int nd, int sl, float hv[8]) {
        // store fp16 h for link head
        uint4 packed;
        {
            __half2 p0 = __floats2half2_rn(hv[0], hv[1]);
            __half2 p1 = __floats2half2_rn(hv[2], hv[3]);
            __half2 p2 = __floats2half2_rn(hv[4], hv[5]);
            __half2 p3 = __floats2half2_rn(hv[6], hv[7]);
            packed.x = *(uint32_t*)&p0; packed.y = *(uint32_t*)&p1;
            packed.z = *(uint32_t*)&p2; packed.w = *(uint32_t*)&p3;
        }
        *(uint4*)&g_hh[(size_t)nd * 128 + sl * 8] = packed;

        float r[8];
#pragma unroll
        for (int j = 0; j < 8; j++) r[j] = fmaxf(hv[j], 0.0f);
        int k0 = sl * 8;

        float logits[N_CLS];
#pragma unroll
        for (int c = 0; c < N_CLS; c++) {
            float p = 0.0f;
#pragma unroll
            for (int j = 0; j < 8; j++) p += r[j] * __ldg(&Wc[(k0 + j) * N_CLS + c]);
#pragma unroll
            for (int o = 8; o > 0; o >>= 1) p += __shfl_xor_sync(0xffffffffu, p, o);
            logits[c] = p + __ldg(&bc[c]);
        }

        float m = logits[0];
#pragma unroll
        for (int c = 1; c < N_CLS; c++) m = fmaxf(m, logits[c]);
        float se = 0.0f;
#pragma unroll
        for (int c = 0; c < N_CLS; c++) se += expf(logits[c] - m);
        float lse = m + logf(se);

        if (sl < N_CLS) {
            float val = logits[0];
#pragma unroll
            for (int c = 1; c < N_CLS; c++) if (sl == c) val = logits[c];
            out[(size_t)nd * N_CLS + sl] = val - lse;
        }
    });
}

// ---------------- link head: 2 edges per warp, fp16 h gathers ----------------
__global__ void k_link(const int* __restrict__ ep, const int* __restrict__ en,
                       const float* __restrict__ Wl, const float* __restrict__ bl,
                       float* __restrict__ out) {
    int gw = (blockIdx.x * blockDim.x + threadIdx.x) >> 5;
    int lane = threadIdx.x & 31;
    int eidx = 2 * gw + (lane >> 4);
    int sl = lane & 15;
    if (eidx >= N_EP + N_EN) return;

    int s, d;
    float* o;
    if (eidx < N_EP) {
        s = ep[eidx]; d = ep[N_EP + eidx]; o = out + eidx;
    } else {
        int e2 = eidx - N_EP;
        s = en[e2]; d = en[N_EN + e2]; o = out + N_EP + e2;
    }

    const uint4* xh = (const uint4*)g_hh;
    uint4 us = __ldg(&xh[(size_t)s * 16 + sl]);
    uint4 ud = __ldg(&xh[(size_t)d * 16 + sl]);

    float hs[8] = {0,0,0,0,0,0,0,0}, hd[8] = {0,0,0,0,0,0,0,0};
    fma8(us, 1.0f, hs);
    fma8(ud, 1.0f, hd);

    float4 w0 = *(const float4*)&Wl[sl * 8];
    float4 w1 = *(const float4*)&Wl[sl * 8 + 4];
    float4 w2 = *(const float4*)&Wl[128 + sl * 8];
    float4 w3 = *(const float4*)&Wl[128 + sl * 8 + 4];

    float p = hs[0] * w0.x + hs[1] * w0.y + hs[2] * w0.z + hs[3] * w0.w
            + hs[4] * w1.x + hs[5] * w1.y + hs[6] * w1.z + hs[7] * w1.w
            + hd[0] * w2.x + hd[1] * w2.y + hd[2] * w2.z + hd[3] * w2.w
            + hd[4] * w3.x + hd[5] * w3.y + hd[6] * w3.z + hd[7] * w3.w;
#pragma unroll
    for (int o2 = 8; o2 > 0; o2 >>= 1) p += __shfl_xor_sync(0xffffffffu, p, o2);

    if (sl == 0) *o = p + bl[0];
}

// ---------------- launch ----------------
extern "C" void kernel_launch(void* const* d_in, const int* in_sizes, int n_in,
                              void* d_out, int out_size) {
    const float* x   = (const float*)d_in[0];
    const int*   ei  = (const int*)d_in[1];
    const int*   ep  = (const int*)d_in[2];
    const int*   en  = (const int*)d_in[3];
    const float* W1  = (const float*)d_in[4];
    const float* b1  = (const float*)d_in[5];
    const float* W2  = (const float*)d_in[6];
    const float* b2  = (const float*)d_in[7];
    const float* Wc  = (const float*)d_in[8];
    const float* bc  = (const float*)d_in[9];
    const float* Wl  = (const float*)d_in[10];
    const float* bl  = (const float*)d_in[11];
    float* out = (float*)d_out;

    const int GEMM_GRID = (N_NODES + 127) / 128;
    const int AGG_GRID  = N_NODES / 16;                   // 16 nodes/block
    const int LINK_GRID = ((N_EP + N_EN) / 2 + 7) / 8;    // 2 edges/warp

    // graph preprocessing (cursor doubles as degree count)
    k_zero<<<(N_NODES + 255) / 256, 256>>>();
    k_bucket<<<N_EDGES / 256, 256>>>(ei);
    k_dinv<<<(N_NODES + 255) / 256, 256>>>();

    // layer 1: tmph = fp16(x @ W1) ; h = relu(agg(tmph) + b1)  (fp32)
    k_gemm_tf32<IN_CH, false><<<GEMM_GRID, 256>>>(x, W1);
    k_agg_relu<<<AGG_GRID, 256>>>(b1);

    // layer 2: tmph = fp16(h @ W2) ; agg + node head fused, h stored fp16
    k_gemm_tf32<HID, true><<<GEMM_GRID, 256>>>(nullptr, W2);
    k_agg_nodehead<<<AGG_GRID, 256>>>(b2, Wc, bc, out);

    // link head
    k_link<<<LINK_GRID, 256>>>(ep, en, Wl, bl, out + NODE_OUT_ELEMS);
}

// round 11
// speedup vs baseline: 2.2399x; 1.0765x over previous
#include <cuda_runtime.h>
#include <cuda_fp16.h>
#include <cstdint>

#define N_NODES 100000
#define N_EDGES 1600000
#define N_EP    200000
#define N_EN    200000
#define IN_CH   256
#define HID     128
#define N_CLS   10
#define CAP     64
#define NODE_OUT_ELEMS (N_NODES * N_CLS)

// ---------------- static device scratch (no allocation allowed) ----------------
__device__ int    g_cursor[N_NODES];                  // degree counts / bucket cursor
__device__ float  g_dinv[N_NODES];
__device__ int    g_srcbuf[(size_t)N_NODES * CAP];    // 25.6 MB
__device__ __half g_tmph[(size_t)N_NODES * 128];      // 25.6 MB  (x@W buffer, fp16)
__device__ __half g_hh[(size_t)N_NODES * 128];        // 25.6 MB  (h buffer, fp16; reused h1 then h2)

// ---------------- graph preprocessing ----------------
__global__ void k_zero() {
    int i = blockIdx.x * blockDim.x + threadIdx.x;
    if (i < N_NODES) g_cursor[i] = 0;
}

__global__ void k_bucket(const int* __restrict__ ei) {
    int i = blockIdx.x * blockDim.x + threadIdx.x;
    if (i < N_EDGES) {
        int d = ei[N_EDGES + i];
        int slot = atomicAdd(&g_cursor[d], 1);
        if (slot < CAP) g_srcbuf[(size_t)d * CAP + slot] = ei[i];
    }
}

__global__ void k_dinv() {
    int i = blockIdx.x * blockDim.x + threadIdx.x;
    if (i < N_NODES) g_dinv[i] = rsqrtf((float)g_cursor[i] + 1.0f);
}

// ---------------- fp16 tensor-core GEMM: g_tmph[N,128] = fp16(A[N,K] @ W[K,128]) ----------------
__device__ __forceinline__ uint32_t packh2(float a, float b) {
    __half2 h = __floats2half2_rn(a, b);
    return *(uint32_t*)&h;
}

// 128x128 tile, 256 threads = 8 warps (4 m x 2 n), warp tile 32x64.
// mma.m16n8k16 fp16 with fp32 accum. Smem holds k-pair-packed half2:
// Asp[k2][row], Bsp[k2][col], stride 136 -> conflict-free fragment loads.
template <int K, bool USE_H>
__global__ void __launch_bounds__(256, 2) k_gemm_f16(const float* __restrict__ A,
                                                     const float* __restrict__ W) {
    constexpr int KC = 32;    // k per chunk
    constexpr int KC2 = 16;   // half2 (k-pairs) per chunk
    __shared__ uint32_t Asp[KC2][136];
    __shared__ uint32_t Bsp[KC2][136];
    int node0 = blockIdx.x * 128;
    int tid  = threadIdx.x;
    int wid  = tid >> 5, lane = tid & 31;
    int wm   = wid >> 1, wn = wid & 1;
    int rb   = wm * 32,  cb = wn * 64;
    int gid  = lane >> 2, tig = lane & 3;

    float acc[2][8][4];
#pragma unroll
    for (int mi = 0; mi < 2; mi++)
#pragma unroll
        for (int ni = 0; ni < 8; ni++)
#pragma unroll
            for (int c = 0; c < 4; c++) acc[mi][ni][c] = 0.0f;

    for (int kc = 0; kc < K; kc += KC) {
        // ---- stage A (128 rows x 32 k) into Asp[k2][row] ----
#pragma unroll
        for (int j = 0; j < 2; j++) {
            int e = tid + j * 256;
            int row = e >> 2, quad = e & 3;     // quad owns 8 k's = 4 half2
            int gr = node0 + row; if (gr >= N_NODES) gr = N_NODES - 1;
            if (USE_H) {
                uint4 u = *(const uint4*)&g_hh[(size_t)gr * K + kc + quad * 8];
                Asp[quad * 4 + 0][row] = u.x;
                Asp[quad * 4 + 1][row] = u.y;
                Asp[quad * 4 + 2][row] = u.z;
                Asp[quad * 4 + 3][row] = u.w;
            } else {
                const float* src = &A[(size_t)gr * K + kc + quad * 8];
                float4 v0 = *(const float4*)src;
                float4 v1 = *(const float4*)(src + 4);
                Asp[quad * 4 + 0][row] = packh2(v0.x, v0.y);
                Asp[quad * 4 + 1][row] = packh2(v0.z, v0.w);
                Asp[quad * 4 + 2][row] = packh2(v1.x, v1.y);
                Asp[quad * 4 + 3][row] = packh2(v1.z, v1.w);
            }
        }
        // ---- stage B (32 k x 128 cols) into Bsp[k2][col] (STS.128) ----
#pragma unroll
        for (int j = 0; j < 2; j++) {
            int e = tid + j * 256;
            int kr2 = e >> 5, c4 = (e & 31) * 4;
            const float* wlo = &W[(size_t)(kc + 2 * kr2) * 128 + c4];
            const float* whi = &W[(size_t)(kc + 2 * kr2 + 1) * 128 + c4];
            float4 lo = *(const float4*)wlo;
            float4 hi = *(const float4*)whi;
            uint4 o;
            o.x = packh2(lo.x, hi.x);
            o.y = packh2(lo.y, hi.y);
            o.z = packh2(lo.z, hi.z);
            o.w = packh2(lo.w, hi.w);
            *(uint4*)&Bsp[kr2][c4] = o;
        }
        __syncthreads();

#pragma unroll
        for (int k0 = 0; k0 < KC2; k0 += 8) {   // two k16 steps per chunk
            uint32_t a[2][4];
#pragma unroll
            for (int mi = 0; mi < 2; mi++) {
                int r0 = rb + mi * 16 + gid;
                a[mi][0] = Asp[k0 + tig    ][r0];
                a[mi][1] = Asp[k0 + tig    ][r0 + 8];
                a[mi][2] = Asp[k0 + tig + 4][r0];
                a[mi][3] = Asp[k0 + tig + 4][r0 + 8];
            }
#pragma unroll
            for (int ni = 0; ni < 8; ni++) {
                uint32_t b0 = Bsp[k0 + tig    ][cb + ni * 8 + gid];
                uint32_t b1 = Bsp[k0 + tig + 4][cb + ni * 8 + gid];
#pragma unroll
                for (int mi = 0; mi < 2; mi++) {
                    asm volatile(
                        "mma.sync.aligned.m16n8k16.row.col.f32.f16.f16.f32 "
                        "{%0,%1,%2,%3}, {%4,%5,%6,%7}, {%8,%9}, {%0,%1,%2,%3};"
                        : "+f"(acc[mi][ni][0]), "+f"(acc[mi][ni][1]),
                          "+f"(acc[mi][ni][2]), "+f"(acc[mi][ni][3])
                        : "r"(a[mi][0]), "r"(a[mi][1]), "r"(a[mi][2]), "r"(a[mi][3]),
                          "r"(b0), "r"(b1));
                }
            }
        }
        __syncthreads();
    }

    // epilogue -> fp16: c0,c1 at (row=gid, col=2*tig), c2,c3 at row+8
#pragma unroll
    for (int mi = 0; mi < 2; mi++) {
        int r0 = node0 + rb + mi * 16 + gid;
#pragma unroll
        for (int ni = 0; ni < 8; ni++) {
            int c0 = cb + ni * 8 + tig * 2;
            if (r0 < N_NODES)
                *(uint32_t*)&g_tmph[(size_t)r0 * 128 + c0] = packh2(acc[mi][ni][0], acc[mi][ni][1]);
            if (r0 + 8 < N_NODES)
                *(uint32_t*)&g_tmph[(size_t)(r0 + 8) * 128 + c0] = packh2(acc[mi][ni][2], acc[mi][ni][3]);
        }
    }
}

// ---------------- aggregation with block-staged (src, weight) pairs ----------------
__device__ __forceinline__ void fma8(uint4 u, float wt, float acc[8]) {
    __half2 h0 = *(__half2*)&u.x, h1 = *(__half2*)&u.y;
    __half2 h2 = *(__half2*)&u.z, h3 = *(__half2*)&u.w;
    float2 f0 = __half22float2(h0), f1 = __half22float2(h1);
    float2 f2 = __half22float2(h2), f3 = __half22float2(h3);
    acc[0] += f0.x * wt; acc[1] += f0.y * wt; acc[2] += f1.x * wt; acc[3] += f1.y * wt;
    acc[4] += f2.x * wt; acc[5] += f2.y * wt; acc[6] += f3.x * wt; acc[7] += f3.y * wt;
}

struct SW { int s; float w; };

template <typename EPILOG>
__device__ __forceinline__ void agg_block(const float* __restrict__ bias, EPILOG epi) {
    __shared__ SW    pairs[16][CAP];     // 8 KB
    __shared__ int   scnt[16];
    __shared__ float sdv[16];

    int tid = threadIdx.x;
    int nb = blockIdx.x * 16;

    if (tid < 16) {
        int c = g_cursor[nb + tid];
        scnt[tid] = c > CAP ? CAP : c;
        sdv[tid] = g_dinv[nb + tid];
    }
    __syncthreads();

#pragma unroll
    for (int j = 0; j < 4; j++) {
        int i = tid + j * 256;
        int n = i >> 6, e = i & 63;
        int s = nb + n;
        float w = 0.0f;
        if (e < scnt[n]) {
            s = __ldg(&g_srcbuf[(size_t)(nb + n) * CAP + e]);
            w = __ldg(&g_dinv[s]) * sdv[n];
        }
        pairs[n][e].s = s;
        pairs[n][e].w = w;
    }
    __syncthreads();

    int lane = tid & 31;
    int nloc = 2 * (tid >> 5) + (lane >> 4);
    int sl = lane & 15;
    int nd = nb + nloc;

    const uint4* xwh = (const uint4*)g_tmph;
    float dv = sdv[nloc];
    float acc[8];
#pragma unroll
    for (int j = 0; j < 8; j++) acc[j] = 0.0f;

    fma8(__ldg(&xwh[(size_t)nd * 16 + sl]), dv * dv, acc);

    int cnt = scnt[nloc];
    int cnt_other = __shfl_xor_sync(0xffffffffu, cnt, 16);
    int cntmax = cnt > cnt_other ? cnt : cnt_other;
    cntmax = (cntmax + 3) & ~3;

    for (int e = 0; e < cntmax; e += 4) {
        SW p0 = pairs[nloc][e];
        SW p1 = pairs[nloc][e + 1];
        SW p2 = pairs[nloc][e + 2];
        SW p3 = pairs[nloc][e + 3];
        uint4 v0 = __ldg(&xwh[(size_t)p0.s * 16 + sl]);
        uint4 v1 = __ldg(&xwh[(size_t)p1.s * 16 + sl]);
        uint4 v2 = __ldg(&xwh[(size_t)p2.s * 16 + sl]);
        uint4 v3 = __ldg(&xwh[(size_t)p3.s * 16 + sl]);
        fma8(v0, p0.w, acc);
        fma8(v1, p1.w, acc);
        fma8(v2, p2.w, acc);
        fma8(v3, p3.w, acc);
    }

    float4 b0 = *(const float4*)&bias[sl * 8];
    float4 b1 = *(const float4*)&bias[sl * 8 + 4];
    acc[0] += b0.x; acc[1] += b0.y; acc[2] += b0.z; acc[3] += b0.w;
    acc[4] += b1.x; acc[5] += b1.y; acc[6] += b1.z; acc[7] += b1.w;

    epi(nd, sl, acc);
}

__device__ __forceinline__ void store_h16(int nd, int sl, const float hv[8]) {
    uint4 packed;
    packed.x = packh2(hv[0], hv[1]);
    packed.y = packh2(hv[2], hv[3]);
    packed.z = packh2(hv[4], hv[5]);
    packed.w = packh2(hv[6], hv[7]);
    *(uint4*)&g_hh[(size_t)nd * 128 + sl * 8] = packed;
}

// layer-1: h1 = relu(agg + b1), stored fp16 (gemm2 input)
__global__ void __launch_bounds__(256) k_agg_relu(const float* __restrict__ bias) {
    agg_block(bias, [](int nd, int sl, float acc[8]) {
#pragma unroll
        for (int j = 0; j < 8; j++) acc[j] = fmaxf(acc[j], 0.0f);
        store_h16(nd, sl, acc);
    });
}

// layer-2 aggregation + node head; h2 stored fp16 (link head input)
__global__ void __launch_bounds__(256) k_agg_nodehead(const float* __restrict__ bias,
                               const float* __restrict__ Wc, const float* __restrict__ bc,
                               float* __restrict__ out) {
    agg_block(bias, [Wc, bc, out](int nd, int sl, float hv[8]) {
        store_h16(nd, sl, hv);

        float r[8];
#pragma unroll
        for (int j = 0; j < 8; j++) r[j] = fmaxf(hv[j], 0.0f);
        int k0 = sl * 8;

        float logits[N_CLS];
#pragma unroll
        for (int c = 0; c < N_CLS; c++) {
            float p = 0.0f;
#pragma unroll
            for (int j = 0; j < 8; j++) p += r[j] * __ldg(&Wc[(k0 + j) * N_CLS + c]);
#pragma unroll
            for (int o = 8; o > 0; o >>= 1) p += __shfl_xor_sync(0xffffffffu, p, o);
            logits[c] = p + __ldg(&bc[c]);
        }

        float m = logits[0];
#pragma unroll
        for (int c = 1; c < N_CLS; c++) m = fmaxf(m, logits[c]);
        float se = 0.0f;
#pragma unroll
        for (int c = 0; c < N_CLS; c++) se += expf(logits[c] - m);
        float lse = m + logf(se);

        if (sl < N_CLS) {
            float val = logits[0];
#pragma unroll
            for (int c = 1; c < N_CLS; c++) if (sl == c) val = logits[c];
            out[(size_t)nd * N_CLS + sl] = val - lse;
        }
    });
}

// ---------------- link head: 2 edges per warp, fp16 h gathers ----------------
__global__ void k_link(const int* __restrict__ ep, const int* __restrict__ en,
                       const float* __restrict__ Wl, const float* __restrict__ bl,
                       float* __restrict__ out) {
    int gw = (blockIdx.x * blockDim.x + threadIdx.x) >> 5;
    int lane = threadIdx.x & 31;
    int eidx = 2 * gw + (lane >> 4);
    int sl = lane & 15;
    if (eidx >= N_EP + N_EN) return;

    int s, d;
    float* o;
    if (eidx < N_EP) {
        s = ep[eidx]; d = ep[N_EP + eidx]; o = out + eidx;
    } else {
        int e2 = eidx - N_EP;
        s = en[e2]; d = en[N_EN + e2]; o = out + N_EP + e2;
    }

    const uint4* xh = (const uint4*)g_hh;
    uint4 us = __ldg(&xh[(size_t)s * 16 + sl]);
    uint4 ud = __ldg(&xh[(size_t)d * 16 + sl]);

    float hs[8] = {0,0,0,0,0,0,0,0}, hd[8] = {0,0,0,0,0,0,0,0};
    fma8(us, 1.0f, hs);
    fma8(ud, 1.0f, hd);

    float4 w0 = *(const float4*)&Wl[sl * 8];
    float4 w1 = *(const float4*)&Wl[sl * 8 + 4];
    float4 w2 = *(const float4*)&Wl[128 + sl * 8];
    float4 w3 = *(const float4*)&Wl[128 + sl * 8 + 4];

    float p = hs[0] * w0.x + hs[1] * w0.y + hs[2] * w0.z + hs[3] * w0.w
            + hs[4] * w1.x + hs[5] * w1.y + hs[6] * w1.z + hs[7] * w1.w
            + hd[0] * w2.x + hd[1] * w2.y + hd[2] * w2.z + hd[3] * w2.w
            + hd[4] * w3.x + hd[5] * w3.y + hd[6] * w3.z + hd[7] * w3.w;
#pragma unroll
    for (int o2 = 8; o2 > 0; o2 >>= 1) p += __shfl_xor_sync(0xffffffffu, p, o2);

    if (sl == 0) *o = p + bl[0];
}

// ---------------- launch ----------------
extern "C" void kernel_launch(void* const* d_in, const int* in_sizes, int n_in,
                              void* d_out, int out_size) {
    const float* x   = (const float*)d_in[0];
    const int*   ei  = (const int*)d_in[1];
    const int*   ep  = (const int*)d_in[2];
    const int*   en  = (const int*)d_in[3];
    const float* W1  = (const float*)d_in[4];
    const float* b1  = (const float*)d_in[5];
    const float* W2  = (const float*)d_in[6];
    const float* b2  = (const float*)d_in[7];
    const float* Wc  = (const float*)d_in[8];
    const float* bc  = (const float*)d_in[9];
    const float* Wl  = (const float*)d_in[10];
    const float* bl  = (const float*)d_in[11];
    float* out = (float*)d_out;

    const int GEMM_GRID = (N_NODES + 127) / 128;
    const int AGG_GRID  = N_NODES / 16;
    const int LINK_GRID = ((N_EP + N_EN) / 2 + 7) / 8;

    // graph preprocessing (cursor doubles as degree count)
    k_zero<<<(N_NODES + 255) / 256, 256>>>();
    k_bucket<<<N_EDGES / 256, 256>>>(ei);
    k_dinv<<<(N_NODES + 255) / 256, 256>>>();

    // layer 1: tmph = fp16(x @ W1) ; h1 = relu(agg(tmph) + b1) -> fp16
    k_gemm_f16<IN_CH, false><<<GEMM_GRID, 256>>>(x, W1);
    k_agg_relu<<<AGG_GRID, 256>>>(b1);

    // layer 2: tmph = fp16(h1 @ W2) ; agg + node head fused, h2 -> fp16
    k_gemm_f16<HID, true><<<GEMM_GRID, 256>>>(nullptr, W2);
    k_agg_nodehead<<<AGG_GRID, 256>>>(b2, Wc, bc, out);

    // link head
    k_link<<<LINK_GRID, 256>>>(ep, en, Wl, bl, out + NODE_OUT_ELEMS);
}